// round 3
// baseline (speedup 1.0000x reference)
#include <cuda_runtime.h>

#define NN 50000
#define NE 800000
#define NT 850000   // NE + NN self loops
#define NG 512

// ---------------- scratch (device globals; no allocation allowed) ----------------
__device__ float    d_xl1[NN * 128];
__device__ float    d_xr1[NN * 128];
__device__ float    d_acc1[NN * 128];   // accum -> h1 (in place)
__device__ float    d_xl2[NN * 64];
__device__ float    d_xr2[NN * 64];
__device__ float    d_acc2[NN * 64];    // accum -> h2 (in place)
__device__ float    d_score1[NT * 4];
__device__ float    d_score2[NT];
__device__ unsigned d_smax1[NN * 4];
__device__ unsigned d_smax2[NN];
__device__ float    d_den1[NN * 4];
__device__ float    d_den2[NN];
__device__ float    d_loopa[NN * 3];    // self-loop edge attr (mean of incoming)
__device__ float    d_nsum[NN * 3];
__device__ float    d_cntv[NN];
__device__ float    d_pool[NG * 64];
__device__ float    d_gcnt[NG];

// order-preserving float<->uint for atomicMax on signed floats
__device__ __forceinline__ unsigned fenc(float f) {
    unsigned u = __float_as_uint(f);
    return (u & 0x80000000u) ? ~u : (u | 0x80000000u);
}
__device__ __forceinline__ float fdec(unsigned u) {
    u = (u & 0x80000000u) ? (u & 0x7fffffffu) : ~u;
    return __uint_as_float(u);
}

// ---------------- zero init (graph replays need fresh accumulators) ----------------
__global__ void zero_small_kernel() {
    int i = blockIdx.x * 256 + threadIdx.x;
    if (i < NN * 3) d_nsum[i] = 0.f;
    if (i < NN)     { d_cntv[i] = 0.f; d_smax2[i] = 0u; d_den2[i] = 0.f; }
    if (i < NN * 4) { d_smax1[i] = 0u; d_den1[i] = 0.f; }
    if (i < NG * 64) d_pool[i] = 0.f;
    if (i < NG)      d_gcnt[i] = 0.f;
}
__global__ void zero_acc_kernel() {
    int i = blockIdx.x * 256 + threadIdx.x;
    if (i < NN * 128) d_acc1[i] = 0.f;
    if (i < NN * 64)  d_acc2[i] = 0.f;
}

// ---------------- self-loop attr = mean of incoming edge attrs ----------------
__global__ void loop_accum_kernel(const int* __restrict__ ei, const float* __restrict__ ea) {
    int e = blockIdx.x * 256 + threadIdx.x;
    if (e >= NE) return;
    int d = ei[NE + e];
    atomicAdd(&d_cntv[d], 1.f);
    atomicAdd(&d_nsum[d * 3 + 0], ea[e * 3 + 0]);
    atomicAdd(&d_nsum[d * 3 + 1], ea[e * 3 + 1]);
    atomicAdd(&d_nsum[d * 3 + 2], ea[e * 3 + 2]);
}
__global__ void loop_fin_kernel() {
    int v = blockIdx.x * 256 + threadIdx.x;
    if (v >= NN) return;
    float c = fmaxf(d_cntv[v], 1.f);
    d_loopa[v * 3 + 0] = d_nsum[v * 3 + 0] / c;
    d_loopa[v * 3 + 1] = d_nsum[v * 3 + 1] / c;
    d_loopa[v * 3 + 2] = d_nsum[v * 3 + 2] / c;
}

// ---------------- node transform GEMM: Y[n,M] = X[n,128] @ W[M,128]^T + b ----------------
// 256 threads; W transposed into smem (conflict-free), X tile in smem.
// thread: 2 outputs x 4 nodes; per k: 1 LDS.64 (w) + 1 LDS.128 (x) + 8 FFMA.
template<int M, int TILE>
__global__ void gemm_xt_kernel(const float* __restrict__ X, const float* __restrict__ W,
                               const float* __restrict__ b, float* __restrict__ Y, int n) {
    extern __shared__ float sm[];
    float* Ws = sm;                          // [128][M+2]
    float* Xs = sm + 128 * (M + 2);          // [128][TILE+4]
    const int tid = threadIdx.x;

    for (int idx = tid; idx < M * 128; idx += 256) {
        int j = idx >> 7, k = idx & 127;
        Ws[k * (M + 2) + j] = W[idx];
    }
    int base = blockIdx.x * TILE;
    for (int idx = tid; idx < TILE * 128; idx += 256) {
        int t = idx >> 7, k = idx & 127;
        int node = base + t;
        Xs[k * (TILE + 4) + t] = (node < n) ? X[node * 128 + k] : 0.f;
    }
    __syncthreads();

    const int JG = M / 2;
    int j0 = (tid % JG) * 2;
    int t0 = (tid / JG) * 4;
    float a00 = 0, a01 = 0, a10 = 0, a11 = 0, a20 = 0, a21 = 0, a30 = 0, a31 = 0;
#pragma unroll 8
    for (int k = 0; k < 128; k++) {
        float2 wv = *reinterpret_cast<const float2*>(&Ws[k * (M + 2) + j0]);
        float4 xv = *reinterpret_cast<const float4*>(&Xs[k * (TILE + 4) + t0]);
        a00 += xv.x * wv.x; a01 += xv.x * wv.y;
        a10 += xv.y * wv.x; a11 += xv.y * wv.y;
        a20 += xv.z * wv.x; a21 += xv.z * wv.y;
        a30 += xv.w * wv.x; a31 += xv.w * wv.y;
    }
    float b0 = b[j0], b1v = b[j0 + 1];
    float ar[4][2] = {{a00, a01}, {a10, a11}, {a20, a21}, {a30, a31}};
#pragma unroll
    for (int t = 0; t < 4; t++) {
        int node = base + t0 + t;
        if (node < n) {
            float2 o; o.x = ar[t][0] + b0; o.y = ar[t][1] + b1v;
            *reinterpret_cast<float2*>(&Y[node * M + j0]) = o;
        }
    }
}

// ---------------- edge helpers ----------------
__device__ __forceinline__ void edge_info(int e, const int* __restrict__ ei,
                                          const float* __restrict__ ea,
                                          int& s, int& d, float& a0, float& a1, float& a2) {
    if (e < NE) {
        s = ei[e]; d = ei[NE + e];
        a0 = ea[e * 3 + 0]; a1 = ea[e * 3 + 1]; a2 = ea[e * 3 + 2];
    } else {
        int v = e - NE; s = v; d = v;
        a0 = d_loopa[v * 3 + 0]; a1 = d_loopa[v * 3 + 1]; a2 = d_loopa[v * 3 + 2];
    }
}
__device__ __forceinline__ void edge_sd(int e, const int* __restrict__ ei, int& s, int& d) {
    if (e < NE) { s = ei[e]; d = ei[NE + e]; }
    else        { s = e - NE; d = s; }
}

// ---------------- layer 1: score pass (4 heads x 32 ch, warp per edge) ----------------
__global__ void score1_kernel(const int* __restrict__ ei, const float* __restrict__ ea,
                              const float* __restrict__ We, const float* __restrict__ att) {
    int e = (blockIdx.x * blockDim.x + threadIdx.x) >> 5;
    int lane = threadIdx.x & 31;
    if (e >= NT) return;
    int s, d; float a0, a1, a2;
    edge_info(e, ei, ea, s, d, a0, a1, a2);
    float sc[4];
#pragma unroll
    for (int h = 0; h < 4; h++) {
        int j = h * 32 + lane;
        float eev = __ldg(&We[j * 3 + 0]) * a0 + __ldg(&We[j * 3 + 1]) * a1 + __ldg(&We[j * 3 + 2]) * a2;
        float m = d_xl1[s * 128 + j] + d_xr1[d * 128 + j] + eev;
        m = (m > 0.f) ? m : 0.2f * m;
        float v = m * __ldg(&att[j]);
#pragma unroll
        for (int off = 16; off > 0; off >>= 1) v += __shfl_xor_sync(0xffffffffu, v, off);
        sc[h] = v;
    }
    if (lane < 4) {
        d_score1[e * 4 + lane] = sc[lane];
        atomicMax(&d_smax1[d * 4 + lane], fenc(sc[lane]));
    }
}

// ---------------- layer 1: accumulate pass ----------------
__global__ void accum1_kernel(const int* __restrict__ ei) {
    int e = (blockIdx.x * blockDim.x + threadIdx.x) >> 5;
    int lane = threadIdx.x & 31;
    if (e >= NT) return;
    int s, d; edge_sd(e, ei, s, d);
    float w[4];
#pragma unroll
    for (int h = 0; h < 4; h++)
        w[h] = __expf(d_score1[e * 4 + h] - fdec(d_smax1[d * 4 + h]));
    if (lane < 4) atomicAdd(&d_den1[d * 4 + lane], w[lane]);
#pragma unroll
    for (int h = 0; h < 4; h++) {
        int j = h * 32 + lane;
        atomicAdd(&d_acc1[d * 128 + j], w[h] * d_xl1[s * 128 + j]);
    }
}

// ---------------- layer 1: normalize + bias + ELU (in place -> h1) ----------------
__global__ void fin1_kernel(const float* __restrict__ b1) {
    int idx = blockIdx.x * 256 + threadIdx.x;
    if (idx >= NN * 128) return;
    int n = idx >> 7, j = idx & 127, h = j >> 5;
    float v = d_acc1[idx] / d_den1[n * 4 + h] + __ldg(&b1[j]);
    d_acc1[idx] = (v > 0.f) ? v : (__expf(v) - 1.f);
}

// ---------------- layer 2: score pass (1 head x 64 ch) ----------------
__global__ void score2_kernel(const int* __restrict__ ei, const float* __restrict__ ea,
                              const float* __restrict__ We, const float* __restrict__ att) {
    int e = (blockIdx.x * blockDim.x + threadIdx.x) >> 5;
    int lane = threadIdx.x & 31;
    if (e >= NT) return;
    int s, d; float a0, a1, a2;
    edge_info(e, ei, ea, s, d, a0, a1, a2);
    float v = 0.f;
#pragma unroll
    for (int half = 0; half < 2; half++) {
        int j = half * 32 + lane;
        float eev = __ldg(&We[j * 3 + 0]) * a0 + __ldg(&We[j * 3 + 1]) * a1 + __ldg(&We[j * 3 + 2]) * a2;
        float m = d_xl2[s * 64 + j] + d_xr2[d * 64 + j] + eev;
        m = (m > 0.f) ? m : 0.2f * m;
        v += m * __ldg(&att[j]);
    }
#pragma unroll
    for (int off = 16; off > 0; off >>= 1) v += __shfl_xor_sync(0xffffffffu, v, off);
    if (lane == 0) {
        d_score2[e] = v;
        atomicMax(&d_smax2[d], fenc(v));
    }
}

__global__ void accum2_kernel(const int* __restrict__ ei) {
    int e = (blockIdx.x * blockDim.x + threadIdx.x) >> 5;
    int lane = threadIdx.x & 31;
    if (e >= NT) return;
    int s, d; edge_sd(e, ei, s, d);
    float w = __expf(d_score2[e] - fdec(d_smax2[d]));
    if (lane == 0) atomicAdd(&d_den2[d], w);
#pragma unroll
    for (int half = 0; half < 2; half++) {
        int j = half * 32 + lane;
        atomicAdd(&d_acc2[d * 64 + j], w * d_xl2[s * 64 + j]);
    }
}

// layer 2 normalize + bias + ELU + graph mean-pool accumulation
__global__ void fin2_kernel(const int* __restrict__ batch, const float* __restrict__ b2) {
    int idx = blockIdx.x * 256 + threadIdx.x;
    if (idx >= NN * 64) return;
    int n = idx >> 6, j = idx & 63;
    float v = d_acc2[idx] / d_den2[n] + __ldg(&b2[j]);
    v = (v > 0.f) ? v : (__expf(v) - 1.f);
    d_acc2[idx] = v;
    int g = batch[n];
    atomicAdd(&d_pool[g * 64 + j], v);
    if (j == 0) atomicAdd(&d_gcnt[g], 1.f);
}

// ---------------- head MLP: z = relu([pool/cnt, u] @ Wl^T + bl); out = z @ Wh^T + bh ----------------
__global__ void head_kernel(const float* __restrict__ u,
                            const float* __restrict__ Wl, const float* __restrict__ bl,
                            const float* __restrict__ Wh, const float* __restrict__ bh,
                            float* __restrict__ out) {
    int g = blockIdx.x;
    int j = threadIdx.x;  // 32 threads
    __shared__ float pin[64];
    __shared__ float z[32];
    float cnt = fmaxf(d_gcnt[g], 1.f);
    for (int k = j; k < 64; k += 32) pin[k] = d_pool[g * 64 + k] / cnt;
    __syncthreads();
    float a = __ldg(&bl[j]);
#pragma unroll 8
    for (int k = 0; k < 64; k++) a += pin[k] * __ldg(&Wl[j * 65 + k]);
    a += __ldg(&u[g]) * __ldg(&Wl[j * 65 + 64]);
    z[j] = fmaxf(a, 0.f);
    __syncthreads();
    if (j < 10) {
        float o = __ldg(&bh[j]);
#pragma unroll
        for (int k = 0; k < 32; k++) o += z[k] * __ldg(&Wh[j * 32 + k]);
        out[g * 10 + j] = o;
    }
}

// ---------------- launch ----------------
extern "C" void kernel_launch(void* const* d_in, const int* in_sizes, int n_in,
                              void* d_out, int out_size) {
    const float* x     = (const float*)d_in[0];
    const int*   ei    = (const int*)d_in[1];
    const float* eattr = (const float*)d_in[2];
    const int*   batch = (const int*)d_in[3];
    const float* u     = (const float*)d_in[4];
    const float* Wl1   = (const float*)d_in[5];
    const float* bl1   = (const float*)d_in[6];
    const float* Wr1   = (const float*)d_in[7];
    const float* br1   = (const float*)d_in[8];
    const float* We1   = (const float*)d_in[9];
    const float* att1  = (const float*)d_in[10];
    const float* b1    = (const float*)d_in[11];
    const float* Wl2   = (const float*)d_in[12];
    const float* bl2   = (const float*)d_in[13];
    const float* Wr2   = (const float*)d_in[14];
    const float* br2   = (const float*)d_in[15];
    const float* We2   = (const float*)d_in[16];
    const float* att2  = (const float*)d_in[17];
    const float* b2    = (const float*)d_in[18];
    const float* Wlin  = (const float*)d_in[19];
    const float* blin  = (const float*)d_in[20];
    const float* Wh    = (const float*)d_in[21];
    const float* bh    = (const float*)d_in[22];
    float* out = (float*)d_out;

    // scratch addresses for GEMM in/out
    float *p_xl1, *p_xr1, *p_acc1, *p_xl2, *p_xr2;
    cudaGetSymbolAddress((void**)&p_xl1,  d_xl1);
    cudaGetSymbolAddress((void**)&p_xr1,  d_xr1);
    cudaGetSymbolAddress((void**)&p_acc1, d_acc1);
    cudaGetSymbolAddress((void**)&p_xl2,  d_xl2);
    cudaGetSymbolAddress((void**)&p_xr2,  d_xr2);

    const int SMEM_G1 = (128 * (128 + 2) + 128 * (16 + 4)) * 4;  // 76800
    const int SMEM_G2 = (128 * (64 + 2) + 128 * (32 + 4)) * 4;   // 52224
    cudaFuncSetAttribute(gemm_xt_kernel<128, 16>, cudaFuncAttributeMaxDynamicSharedMemorySize, SMEM_G1);
    cudaFuncSetAttribute(gemm_xt_kernel<64, 32>,  cudaFuncAttributeMaxDynamicSharedMemorySize, SMEM_G2);

    const int EW_BLOCKS = (NT + 7) / 8;  // warp-per-edge, 8 warps/block

    zero_small_kernel<<<(NN * 4 + 255) / 256, 256>>>();
    zero_acc_kernel<<<(NN * 128 + 255) / 256, 256>>>();

    loop_accum_kernel<<<(NE + 255) / 256, 256>>>(ei, eattr);
    loop_fin_kernel<<<(NN + 255) / 256, 256>>>();

    gemm_xt_kernel<128, 16><<<(NN + 15) / 16, 256, SMEM_G1>>>(x, Wl1, bl1, p_xl1, NN);
    gemm_xt_kernel<128, 16><<<(NN + 15) / 16, 256, SMEM_G1>>>(x, Wr1, br1, p_xr1, NN);

    score1_kernel<<<EW_BLOCKS, 256>>>(ei, eattr, We1, att1);
    accum1_kernel<<<EW_BLOCKS, 256>>>(ei);
    fin1_kernel<<<(NN * 128 + 255) / 256, 256>>>(b1);

    gemm_xt_kernel<64, 32><<<(NN + 31) / 32, 256, SMEM_G2>>>(p_acc1, Wl2, bl2, p_xl2, NN);
    gemm_xt_kernel<64, 32><<<(NN + 31) / 32, 256, SMEM_G2>>>(p_acc1, Wr2, br2, p_xr2, NN);

    score2_kernel<<<EW_BLOCKS, 256>>>(ei, eattr, We2, att2);
    accum2_kernel<<<EW_BLOCKS, 256>>>(ei);
    fin2_kernel<<<(NN * 64 + 255) / 256, 256>>>(batch, b2);

    head_kernel<<<NG, 32>>>(u, Wlin, blin, Wh, bh, out);
}

// round 5
// speedup vs baseline: 1.1868x; 1.1868x over previous
#include <cuda_runtime.h>

#define NN 50000
#define NE 800000
#define NT 850000   // NE + NN self loops
#define NG 512

// ---------------- scratch (device globals; no allocation allowed) ----------------
__device__ __align__(16) float d_xl1[NN * 128];
__device__ __align__(16) float d_xr1[NN * 128];
__device__ __align__(16) float d_acc1[NN * 128];   // accum -> h1 (in place)
__device__ __align__(16) float d_xl2[NN * 64];
__device__ __align__(16) float d_xr2[NN * 64];
__device__ __align__(16) float d_acc2[NN * 64];    // accum -> h2 (in place)
__device__ float d_den1[NN * 4];
__device__ float d_den2[NN];
__device__ float d_loopa[NN * 3];    // self-loop edge attr (mean of incoming)
__device__ float d_nsum[NN * 3];
__device__ float d_cntv[NN];
__device__ float d_pool[NG * 64];
__device__ float d_gcnt[NG];

// ---------------- zero init (graph replays need fresh accumulators) ----------------
__global__ void zero_small_kernel() {
    int i = blockIdx.x * 256 + threadIdx.x;
    if (i < NN * 3) d_nsum[i] = 0.f;
    if (i < NN)     { d_cntv[i] = 0.f; d_den2[i] = 0.f; }
    if (i < NN * 4) d_den1[i] = 0.f;
    if (i < NG * 64) d_pool[i] = 0.f;
    if (i < NG)      d_gcnt[i] = 0.f;
}
__global__ void zero_acc_kernel() {
    int i = blockIdx.x * 256 + threadIdx.x;
    if (i < NN * 128) d_acc1[i] = 0.f;
    if (i < NN * 64)  d_acc2[i] = 0.f;
}

// ---------------- self-loop attr = mean of incoming edge attrs ----------------
__global__ void loop_accum_kernel(const int* __restrict__ ei, const float* __restrict__ ea) {
    int e = blockIdx.x * 256 + threadIdx.x;
    if (e >= NE) return;
    int d = ei[NE + e];
    atomicAdd(&d_cntv[d], 1.f);
    atomicAdd(&d_nsum[d * 3 + 0], ea[e * 3 + 0]);
    atomicAdd(&d_nsum[d * 3 + 1], ea[e * 3 + 1]);
    atomicAdd(&d_nsum[d * 3 + 2], ea[e * 3 + 2]);
}
__global__ void loop_fin_kernel() {
    int v = blockIdx.x * 256 + threadIdx.x;
    if (v >= NN) return;
    float c = fmaxf(d_cntv[v], 1.f);
    d_loopa[v * 3 + 0] = d_nsum[v * 3 + 0] / c;
    d_loopa[v * 3 + 1] = d_nsum[v * 3 + 1] / c;
    d_loopa[v * 3 + 2] = d_nsum[v * 3 + 2] / c;
}

// ---------------- node transform GEMM: Y[n,M] = X[n,128] @ W[M,128]^T + b ----------------
template<int M, int TILE>
__global__ void gemm_xt_kernel(const float* __restrict__ X, const float* __restrict__ W,
                               const float* __restrict__ b, float* __restrict__ Y, int n) {
    extern __shared__ float sm[];
    float* Ws = sm;                          // [128][M+2]
    float* Xs = sm + 128 * (M + 2);          // [128][TILE+4]
    const int tid = threadIdx.x;

    for (int idx = tid; idx < M * 128; idx += 256) {
        int j = idx >> 7, k = idx & 127;
        Ws[k * (M + 2) + j] = W[idx];
    }
    int base = blockIdx.x * TILE;
    for (int idx = tid; idx < TILE * 128; idx += 256) {
        int t = idx >> 7, k = idx & 127;
        int node = base + t;
        Xs[k * (TILE + 4) + t] = (node < n) ? X[node * 128 + k] : 0.f;
    }
    __syncthreads();

    const int JG = M / 2;
    int j0 = (tid % JG) * 2;
    int t0 = (tid / JG) * 4;
    float a00 = 0, a01 = 0, a10 = 0, a11 = 0, a20 = 0, a21 = 0, a30 = 0, a31 = 0;
#pragma unroll 8
    for (int k = 0; k < 128; k++) {
        float2 wv = *reinterpret_cast<const float2*>(&Ws[k * (M + 2) + j0]);
        float4 xv = *reinterpret_cast<const float4*>(&Xs[k * (TILE + 4) + t0]);
        a00 += xv.x * wv.x; a01 += xv.x * wv.y;
        a10 += xv.y * wv.x; a11 += xv.y * wv.y;
        a20 += xv.z * wv.x; a21 += xv.z * wv.y;
        a30 += xv.w * wv.x; a31 += xv.w * wv.y;
    }
    float b0 = b[j0], b1v = b[j0 + 1];
    float ar[4][2] = {{a00, a01}, {a10, a11}, {a20, a21}, {a30, a31}};
#pragma unroll
    for (int t = 0; t < 4; t++) {
        int node = base + t0 + t;
        if (node < n) {
            float2 o; o.x = ar[t][0] + b0; o.y = ar[t][1] + b1v;
            *reinterpret_cast<float2*>(&Y[node * M + j0]) = o;
        }
    }
}

// ---------------- edge helper ----------------
__device__ __forceinline__ void edge_info(int e, const int* __restrict__ ei,
                                          const float* __restrict__ ea,
                                          int& s, int& d, float& a0, float& a1, float& a2) {
    if (e < NE) {
        s = ei[e]; d = ei[NE + e];
        a0 = ea[e * 3 + 0]; a1 = ea[e * 3 + 1]; a2 = ea[e * 3 + 2];
    } else {
        int v = e - NE; s = v; d = v;
        a0 = d_loopa[v * 3 + 0]; a1 = d_loopa[v * 3 + 1]; a2 = d_loopa[v * 3 + 2];
    }
}

__device__ __forceinline__ float lrelu(float m) { return (m > 0.f) ? m : 0.2f * m; }

// ---------------- layer 1 FUSED edge pass: score (no max) + exp + accumulate ----------------
// warp per edge; lane owns 4 consecutive channels (float4); head = lane>>3.
__global__ void edge1_fused_kernel(const int* __restrict__ ei, const float* __restrict__ ea,
                                   const float* __restrict__ We, const float* __restrict__ att) {
    __shared__ float sWe[128 * 3];
    __shared__ __align__(16) float sAtt[128];
    int tid = threadIdx.x;
    for (int i = tid; i < 384; i += blockDim.x) sWe[i] = We[i];
    for (int i = tid; i < 128; i += blockDim.x) sAtt[i] = att[i];
    __syncthreads();

    int e = (blockIdx.x * blockDim.x + tid) >> 5;
    if (e >= NT) return;
    int lane = tid & 31;
    int s, d; float a0, a1, a2;
    edge_info(e, ei, ea, s, d, a0, a1, a2);

    int j0 = lane * 4;
    float4 xl = *reinterpret_cast<const float4*>(&d_xl1[s * 128 + j0]);
    float4 xr = *reinterpret_cast<const float4*>(&d_xr1[d * 128 + j0]);
    float4 at = *reinterpret_cast<const float4*>(&sAtt[j0]);

    float m0 = lrelu(xl.x + xr.x + sWe[(j0+0)*3]*a0 + sWe[(j0+0)*3+1]*a1 + sWe[(j0+0)*3+2]*a2);
    float m1 = lrelu(xl.y + xr.y + sWe[(j0+1)*3]*a0 + sWe[(j0+1)*3+1]*a1 + sWe[(j0+1)*3+2]*a2);
    float m2 = lrelu(xl.z + xr.z + sWe[(j0+2)*3]*a0 + sWe[(j0+2)*3+1]*a1 + sWe[(j0+2)*3+2]*a2);
    float m3 = lrelu(xl.w + xr.w + sWe[(j0+3)*3]*a0 + sWe[(j0+3)*3+1]*a1 + sWe[(j0+3)*3+2]*a2);
    float p = m0*at.x + m1*at.y + m2*at.z + m3*at.w;

    // reduce within the 8-lane head group
    p += __shfl_xor_sync(0xffffffffu, p, 1);
    p += __shfl_xor_sync(0xffffffffu, p, 2);
    p += __shfl_xor_sync(0xffffffffu, p, 4);

    float w = __expf(p);   // no max-subtraction: mathematically identical softmax
    if ((lane & 7) == 0) atomicAdd(&d_den1[d * 4 + (lane >> 3)], w);

    float v0 = w * xl.x, v1 = w * xl.y, v2 = w * xl.z, v3 = w * xl.w;
    asm volatile("red.global.add.v4.f32 [%0], {%1, %2, %3, %4};"
                 :: "l"(&d_acc1[d * 128 + j0]), "f"(v0), "f"(v1), "f"(v2), "f"(v3)
                 : "memory");
}

// ---------------- layer 1: normalize + bias + ELU (in place -> h1) ----------------
__global__ void fin1_kernel(const float* __restrict__ b1) {
    int idx = blockIdx.x * 256 + threadIdx.x;
    if (idx >= NN * 128) return;
    int n = idx >> 7, j = idx & 127, h = j >> 5;
    float v = d_acc1[idx] / d_den1[n * 4 + h] + __ldg(&b1[j]);
    d_acc1[idx] = (v > 0.f) ? v : (__expf(v) - 1.f);
}

// ---------------- layer 2 FUSED edge pass (1 head x 64 ch): lane owns 2 channels ----------------
__global__ void edge2_fused_kernel(const int* __restrict__ ei, const float* __restrict__ ea,
                                   const float* __restrict__ We, const float* __restrict__ att) {
    __shared__ float sWe[64 * 3];
    __shared__ __align__(8) float sAtt[64];
    int tid = threadIdx.x;
    for (int i = tid; i < 192; i += blockDim.x) sWe[i] = We[i];
    for (int i = tid; i < 64; i += blockDim.x) sAtt[i] = att[i];
    __syncthreads();

    int e = (blockIdx.x * blockDim.x + tid) >> 5;
    if (e >= NT) return;
    int lane = tid & 31;
    int s, d; float a0, a1, a2;
    edge_info(e, ei, ea, s, d, a0, a1, a2);

    int j0 = lane * 2;
    float2 xl = *reinterpret_cast<const float2*>(&d_xl2[s * 64 + j0]);
    float2 xr = *reinterpret_cast<const float2*>(&d_xr2[d * 64 + j0]);
    float2 at = *reinterpret_cast<const float2*>(&sAtt[j0]);

    float m0 = lrelu(xl.x + xr.x + sWe[(j0+0)*3]*a0 + sWe[(j0+0)*3+1]*a1 + sWe[(j0+0)*3+2]*a2);
    float m1 = lrelu(xl.y + xr.y + sWe[(j0+1)*3]*a0 + sWe[(j0+1)*3+1]*a1 + sWe[(j0+1)*3+2]*a2);
    float p = m0 * at.x + m1 * at.y;

#pragma unroll
    for (int off = 16; off > 0; off >>= 1) p += __shfl_xor_sync(0xffffffffu, p, off);

    float w = __expf(p);
    if (lane == 0) atomicAdd(&d_den2[d], w);

    float v0 = w * xl.x, v1 = w * xl.y;
    asm volatile("red.global.add.v2.f32 [%0], {%1, %2};"
                 :: "l"(&d_acc2[d * 64 + j0]), "f"(v0), "f"(v1)
                 : "memory");
}

// layer 2 normalize + bias + ELU + graph mean-pool accumulation
__global__ void fin2_kernel(const int* __restrict__ batch, const float* __restrict__ b2) {
    int idx = blockIdx.x * 256 + threadIdx.x;
    if (idx >= NN * 64) return;
    int n = idx >> 6, j = idx & 63;
    float v = d_acc2[idx] / d_den2[n] + __ldg(&b2[j]);
    v = (v > 0.f) ? v : (__expf(v) - 1.f);
    int g = batch[n];
    atomicAdd(&d_pool[g * 64 + j], v);
    if (j == 0) atomicAdd(&d_gcnt[g], 1.f);
}

// ---------------- head MLP ----------------
__global__ void head_kernel(const float* __restrict__ u,
                            const float* __restrict__ Wl, const float* __restrict__ bl,
                            const float* __restrict__ Wh, const float* __restrict__ bh,
                            float* __restrict__ out) {
    int g = blockIdx.x;
    int j = threadIdx.x;  // 32 threads
    __shared__ float pin[64];
    __shared__ float z[32];
    float cnt = fmaxf(d_gcnt[g], 1.f);
    for (int k = j; k < 64; k += 32) pin[k] = d_pool[g * 64 + k] / cnt;
    __syncthreads();
    float a = __ldg(&bl[j]);
#pragma unroll 8
    for (int k = 0; k < 64; k++) a += pin[k] * __ldg(&Wl[j * 65 + k]);
    a += __ldg(&u[g]) * __ldg(&Wl[j * 65 + 64]);
    z[j] = fmaxf(a, 0.f);
    __syncthreads();
    if (j < 10) {
        float o = __ldg(&bh[j]);
#pragma unroll
        for (int k = 0; k < 32; k++) o += z[k] * __ldg(&Wh[j * 32 + k]);
        out[g * 10 + j] = o;
    }
}

// ---------------- launch ----------------
extern "C" void kernel_launch(void* const* d_in, const int* in_sizes, int n_in,
                              void* d_out, int out_size) {
    const float* x     = (const float*)d_in[0];
    const int*   ei    = (const int*)d_in[1];
    const float* eattr = (const float*)d_in[2];
    const int*   batch = (const int*)d_in[3];
    const float* u     = (const float*)d_in[4];
    const float* Wl1   = (const float*)d_in[5];
    const float* bl1   = (const float*)d_in[6];
    const float* Wr1   = (const float*)d_in[7];
    const float* br1   = (const float*)d_in[8];
    const float* We1   = (const float*)d_in[9];
    const float* att1  = (const float*)d_in[10];
    const float* b1    = (const float*)d_in[11];
    const float* Wl2   = (const float*)d_in[12];
    const float* bl2   = (const float*)d_in[13];
    const float* Wr2   = (const float*)d_in[14];
    const float* br2   = (const float*)d_in[15];
    const float* We2   = (const float*)d_in[16];
    const float* att2  = (const float*)d_in[17];
    const float* b2    = (const float*)d_in[18];
    const float* Wlin  = (const float*)d_in[19];
    const float* blin  = (const float*)d_in[20];
    const float* Wh    = (const float*)d_in[21];
    const float* bh    = (const float*)d_in[22];
    float* out = (float*)d_out;

    float *p_xl1, *p_xr1, *p_acc1, *p_xl2, *p_xr2;
    cudaGetSymbolAddress((void**)&p_xl1,  d_xl1);
    cudaGetSymbolAddress((void**)&p_xr1,  d_xr1);
    cudaGetSymbolAddress((void**)&p_acc1, d_acc1);
    cudaGetSymbolAddress((void**)&p_xl2,  d_xl2);
    cudaGetSymbolAddress((void**)&p_xr2,  d_xr2);

    const int SMEM_G1 = (128 * (128 + 2) + 128 * (16 + 4)) * 4;  // 76800
    const int SMEM_G2 = (128 * (64 + 2) + 128 * (32 + 4)) * 4;   // 52224
    cudaFuncSetAttribute(gemm_xt_kernel<128, 16>, cudaFuncAttributeMaxDynamicSharedMemorySize, SMEM_G1);
    cudaFuncSetAttribute(gemm_xt_kernel<64, 32>,  cudaFuncAttributeMaxDynamicSharedMemorySize, SMEM_G2);

    const int EW_BLOCKS = (NT + 7) / 8;  // warp-per-edge, 8 warps/block

    zero_small_kernel<<<(NN * 4 + 255) / 256, 256>>>();
    zero_acc_kernel<<<(NN * 128 + 255) / 256, 256>>>();

    loop_accum_kernel<<<(NE + 255) / 256, 256>>>(ei, eattr);
    loop_fin_kernel<<<(NN + 255) / 256, 256>>>();

    gemm_xt_kernel<128, 16><<<(NN + 15) / 16, 256, SMEM_G1>>>(x, Wl1, bl1, p_xl1, NN);
    gemm_xt_kernel<128, 16><<<(NN + 15) / 16, 256, SMEM_G1>>>(x, Wr1, br1, p_xr1, NN);

    edge1_fused_kernel<<<EW_BLOCKS, 256>>>(ei, eattr, We1, att1);
    fin1_kernel<<<(NN * 128 + 255) / 256, 256>>>(b1);

    gemm_xt_kernel<64, 32><<<(NN + 31) / 32, 256, SMEM_G2>>>(p_acc1, Wl2, bl2, p_xl2, NN);
    gemm_xt_kernel<64, 32><<<(NN + 31) / 32, 256, SMEM_G2>>>(p_acc1, Wr2, br2, p_xr2, NN);

    edge2_fused_kernel<<<EW_BLOCKS, 256>>>(ei, eattr, We2, att2);
    fin2_kernel<<<(NN * 64 + 255) / 256, 256>>>(batch, b2);

    head_kernel<<<NG, 32>>>(u, Wlin, blin, Wh, bh, out);
}

// round 7
// speedup vs baseline: 1.8034x; 1.5196x over previous
#include <cuda_runtime.h>

#define NN 50000
#define NE 800000
#define NT 850000   // NE + NN self loops
#define NG 512
#define SCAN_BLK 1024
#define NSCAN ((NN + SCAN_BLK - 1) / SCAN_BLK)   // 49

// ---------------- scratch (device globals; no allocation allowed) ----------------
__device__ __align__(16) float d_xl1[NN * 128];
__device__ __align__(16) float d_xr1[NN * 128];
__device__ __align__(16) float d_h1[NN * 128];
__device__ __align__(16) float d_xl2[NN * 64];
__device__ __align__(16) float d_xr2[NN * 64];
__device__ __align__(16) float4 d_rec[NT];      // CSR records: {src_as_float, a0, a1, a2}
__device__ int   d_cnt[NN];                     // real in-degree
__device__ int   d_off[NN];                     // CSR start offset
__device__ int   d_fill[NN];
__device__ int   d_bsum[NSCAN];
__device__ int   d_boff[NSCAN];
__device__ float d_nsum[NN * 3];
__device__ float d_pool[NG * 64];
__device__ float d_gcnt[NG];

__device__ __forceinline__ float lrelu(float m) { return (m > 0.f) ? m : 0.2f * m; }

// ---------------- zero init (graph replays need fresh accumulators) ----------------
__global__ void zero_kernel() {
    int i = blockIdx.x * 256 + threadIdx.x;
    if (i < NN * 3) d_nsum[i] = 0.f;
    if (i < NN)     { d_cnt[i] = 0; d_fill[i] = 0; }
    if (i < NG * 64) d_pool[i] = 0.f;
    if (i < NG)      d_gcnt[i] = 0.f;
}

// ---------------- histogram + self-loop attr sums ----------------
__global__ void hist_kernel(const int* __restrict__ ei, const float* __restrict__ ea) {
    int e = blockIdx.x * 256 + threadIdx.x;
    if (e >= NE) return;
    int d = ei[NE + e];
    atomicAdd(&d_cnt[d], 1);
    atomicAdd(&d_nsum[d * 3 + 0], ea[e * 3 + 0]);
    atomicAdd(&d_nsum[d * 3 + 1], ea[e * 3 + 1]);
    atomicAdd(&d_nsum[d * 3 + 2], ea[e * 3 + 2]);
}

// ---------------- 2-level exclusive scan of (cnt[v]+1) ----------------
__global__ void scan_part_kernel() {
    __shared__ int wsum[8];
    __shared__ int woff[8];
    int b = blockIdx.x, t = threadIdx.x;
    int lane = t & 31, wid = t >> 5;
    int base = b * SCAN_BLK + t * 4;
    int v0 = (base + 0 < NN) ? d_cnt[base + 0] + 1 : 0;
    int v1 = (base + 1 < NN) ? d_cnt[base + 1] + 1 : 0;
    int v2 = (base + 2 < NN) ? d_cnt[base + 2] + 1 : 0;
    int v3 = (base + 3 < NN) ? d_cnt[base + 3] + 1 : 0;
    int tsum = v0 + v1 + v2 + v3;
    int x = tsum;
#pragma unroll
    for (int o = 1; o < 32; o <<= 1) {
        int y = __shfl_up_sync(0xffffffffu, x, o);
        if (lane >= o) x += y;
    }
    if (lane == 31) wsum[wid] = x;
    __syncthreads();
    if (t == 0) {
        int r = 0;
#pragma unroll
        for (int i = 0; i < 8; i++) { woff[i] = r; r += wsum[i]; }
        d_bsum[b] = r;
    }
    __syncthreads();
    int excl = x - tsum + woff[wid];
    if (base + 0 < NN) d_off[base + 0] = excl;
    if (base + 1 < NN) d_off[base + 1] = excl + v0;
    if (base + 2 < NN) d_off[base + 2] = excl + v0 + v1;
    if (base + 3 < NN) d_off[base + 3] = excl + v0 + v1 + v2;
}

__global__ void scan_top_kernel() {
    __shared__ int s[NSCAN];
    int t = threadIdx.x;
    if (t < NSCAN) s[t] = d_bsum[t];
    __syncthreads();
    if (t == 0) {
        int r = 0;
        for (int i = 0; i < NSCAN; i++) { int v = s[i]; s[i] = r; r += v; }
    }
    __syncthreads();
    if (t < NSCAN) d_boff[t] = s[t];
}

// finalize offsets + write the self-loop record (mean of incoming edge attrs)
__global__ void scan_fin_kernel() {
    int v = blockIdx.x * 256 + threadIdx.x;
    if (v >= NN) return;
    int off = d_off[v] + d_boff[v >> 10];
    d_off[v] = off;
    int c = d_cnt[v];
    float cf = fmaxf((float)c, 1.f);
    float4 r;
    r.x = __int_as_float(v);
    r.y = d_nsum[v * 3 + 0] / cf;
    r.z = d_nsum[v * 3 + 1] / cf;
    r.w = d_nsum[v * 3 + 2] / cf;
    d_rec[off + c] = r;   // self loop goes last
}

// scatter real edges into CSR
__global__ void scatter_kernel(const int* __restrict__ ei, const float* __restrict__ ea) {
    int e = blockIdx.x * 256 + threadIdx.x;
    if (e >= NE) return;
    int s = ei[e], d = ei[NE + e];
    int slot = d_off[d] + atomicAdd(&d_fill[d], 1);
    float4 r;
    r.x = __int_as_float(s);
    r.y = ea[e * 3 + 0];
    r.z = ea[e * 3 + 1];
    r.w = ea[e * 3 + 2];
    d_rec[slot] = r;
}

// ---------------- node transform GEMM: Y[n,M] = X[n,128] @ W[M,128]^T + b ----------------
template<int M, int TILE>
__global__ void gemm_xt_kernel(const float* __restrict__ X, const float* __restrict__ W,
                               const float* __restrict__ b, float* __restrict__ Y, int n) {
    extern __shared__ float sm[];
    float* Ws = sm;                          // [128][M+2]
    float* Xs = sm + 128 * (M + 2);          // [128][TILE+4]
    const int tid = threadIdx.x;

    for (int idx = tid; idx < M * 128; idx += 256) {
        int j = idx >> 7, k = idx & 127;
        Ws[k * (M + 2) + j] = W[idx];
    }
    int base = blockIdx.x * TILE;
    for (int idx = tid; idx < TILE * 128; idx += 256) {
        int t = idx >> 7, k = idx & 127;
        int node = base + t;
        Xs[k * (TILE + 4) + t] = (node < n) ? X[node * 128 + k] : 0.f;
    }
    __syncthreads();

    const int JG = M / 2;
    int j0 = (tid % JG) * 2;
    int t0 = (tid / JG) * 4;
    float a00 = 0, a01 = 0, a10 = 0, a11 = 0, a20 = 0, a21 = 0, a30 = 0, a31 = 0;
#pragma unroll 8
    for (int k = 0; k < 128; k++) {
        float2 wv = *reinterpret_cast<const float2*>(&Ws[k * (M + 2) + j0]);
        float4 xv = *reinterpret_cast<const float4*>(&Xs[k * (TILE + 4) + t0]);
        a00 += xv.x * wv.x; a01 += xv.x * wv.y;
        a10 += xv.y * wv.x; a11 += xv.y * wv.y;
        a20 += xv.z * wv.x; a21 += xv.z * wv.y;
        a30 += xv.w * wv.x; a31 += xv.w * wv.y;
    }
    float b0 = b[j0], b1v = b[j0 + 1];
    float ar[4][2] = {{a00, a01}, {a10, a11}, {a20, a21}, {a30, a31}};
#pragma unroll
    for (int t = 0; t < 4; t++) {
        int node = base + t0 + t;
        if (node < n) {
            float2 o; o.x = ar[t][0] + b0; o.y = ar[t][1] + b1v;
            *reinterpret_cast<float2*>(&Y[node * M + j0]) = o;
        }
    }
}

// ---------------- layer 1 gather: warp per dst node, fully fused ----------------
// score (no max-sub) + exp + weighted accum + normalize + bias + ELU, all in registers.
__global__ void gather1_kernel(const float* __restrict__ We, const float* __restrict__ att,
                               const float* __restrict__ b1) {
    __shared__ float sWe[128 * 3];
    __shared__ __align__(16) float sAtt[128];
    __shared__ __align__(16) float sB[128];
    int tid = threadIdx.x;
    for (int i = tid; i < 384; i += 256) sWe[i] = We[i];
    for (int i = tid; i < 128; i += 256) { sAtt[i] = att[i]; sB[i] = b1[i]; }
    __syncthreads();

    int v = (blockIdx.x * 256 + tid) >> 5;
    if (v >= NN) return;
    int lane = tid & 31;
    int j0 = lane * 4;

    float4 xr = *reinterpret_cast<const float4*>(&d_xr1[v * 128 + j0]);
    float4 at = *reinterpret_cast<const float4*>(&sAtt[j0]);
    float w0 = sWe[j0*3+0], w1 = sWe[j0*3+1], w2 = sWe[j0*3+2];
    float w3 = sWe[j0*3+3], w4 = sWe[j0*3+4], w5 = sWe[j0*3+5];
    float w6 = sWe[j0*3+6], w7 = sWe[j0*3+7], w8 = sWe[j0*3+8];
    float w9 = sWe[j0*3+9], wa = sWe[j0*3+10], wb = sWe[j0*3+11];

    int off = d_off[v];
    int deg = d_cnt[v] + 1;

    float a0 = 0.f, a1 = 0.f, a2 = 0.f, a3 = 0.f, den = 0.f;
    float4 rec = __ldg(&d_rec[off]);
    for (int i = 0; i < deg; i++) {
        int s = __float_as_int(rec.x);
        float ea0 = rec.y, ea1 = rec.z, ea2 = rec.w;
        if (i + 1 < deg) rec = __ldg(&d_rec[off + i + 1]);   // prefetch next
        float4 xl = *reinterpret_cast<const float4*>(&d_xl1[s * 128 + j0]);
        float m0 = lrelu(xl.x + xr.x + w0 * ea0 + w1 * ea1 + w2 * ea2);
        float m1 = lrelu(xl.y + xr.y + w3 * ea0 + w4 * ea1 + w5 * ea2);
        float m2 = lrelu(xl.z + xr.z + w6 * ea0 + w7 * ea1 + w8 * ea2);
        float m3 = lrelu(xl.w + xr.w + w9 * ea0 + wa * ea1 + wb * ea2);
        float p = m0 * at.x + m1 * at.y + m2 * at.z + m3 * at.w;
        p += __shfl_xor_sync(0xffffffffu, p, 1);
        p += __shfl_xor_sync(0xffffffffu, p, 2);
        p += __shfl_xor_sync(0xffffffffu, p, 4);
        float w = __expf(p);
        den += w;
        a0 += w * xl.x; a1 += w * xl.y; a2 += w * xl.z; a3 += w * xl.w;
    }
    float inv = 1.f / den;
    float4 bv = *reinterpret_cast<const float4*>(&sB[j0]);
    float o0 = a0 * inv + bv.x, o1 = a1 * inv + bv.y;
    float o2 = a2 * inv + bv.z, o3 = a3 * inv + bv.w;
    float4 o;
    o.x = (o0 > 0.f) ? o0 : (__expf(o0) - 1.f);
    o.y = (o1 > 0.f) ? o1 : (__expf(o1) - 1.f);
    o.z = (o2 > 0.f) ? o2 : (__expf(o2) - 1.f);
    o.w = (o3 > 0.f) ? o3 : (__expf(o3) - 1.f);
    *reinterpret_cast<float4*>(&d_h1[v * 128 + j0]) = o;
}

// ---------------- layer 2 gather: warp per dst node + pooled accumulation ----------------
__global__ void gather2_kernel(const float* __restrict__ We, const float* __restrict__ att,
                               const float* __restrict__ b2, const int* __restrict__ batch) {
    __shared__ float sWe[64 * 3];
    __shared__ __align__(8) float sAtt[64];
    __shared__ __align__(8) float sB[64];
    int tid = threadIdx.x;
    for (int i = tid; i < 192; i += 256) sWe[i] = We[i];
    for (int i = tid; i < 64; i += 256) { sAtt[i] = att[i]; sB[i] = b2[i]; }
    __syncthreads();

    int v = (blockIdx.x * 256 + tid) >> 5;
    if (v >= NN) return;
    int lane = tid & 31;
    int j0 = lane * 2;

    float2 xr = *reinterpret_cast<const float2*>(&d_xr2[v * 64 + j0]);
    float2 at = *reinterpret_cast<const float2*>(&sAtt[j0]);
    float w0 = sWe[j0*3+0], w1 = sWe[j0*3+1], w2 = sWe[j0*3+2];
    float w3 = sWe[j0*3+3], w4 = sWe[j0*3+4], w5 = sWe[j0*3+5];

    int off = d_off[v];
    int deg = d_cnt[v] + 1;

    float a0 = 0.f, a1 = 0.f, den = 0.f;
    float4 rec = __ldg(&d_rec[off]);
    for (int i = 0; i < deg; i++) {
        int s = __float_as_int(rec.x);
        float ea0 = rec.y, ea1 = rec.z, ea2 = rec.w;
        if (i + 1 < deg) rec = __ldg(&d_rec[off + i + 1]);
        float2 xl = *reinterpret_cast<const float2*>(&d_xl2[s * 64 + j0]);
        float m0 = lrelu(xl.x + xr.x + w0 * ea0 + w1 * ea1 + w2 * ea2);
        float m1 = lrelu(xl.y + xr.y + w3 * ea0 + w4 * ea1 + w5 * ea2);
        float p = m0 * at.x + m1 * at.y;
#pragma unroll
        for (int o = 16; o > 0; o >>= 1) p += __shfl_xor_sync(0xffffffffu, p, o);
        float w = __expf(p);
        den += w;
        a0 += w * xl.x; a1 += w * xl.y;
    }
    float inv = 1.f / den;
    float o0 = a0 * inv + sB[j0], o1 = a1 * inv + sB[j0 + 1];
    o0 = (o0 > 0.f) ? o0 : (__expf(o0) - 1.f);
    o1 = (o1 > 0.f) ? o1 : (__expf(o1) - 1.f);
    int g = __ldg(&batch[v]);
    asm volatile("red.global.add.v2.f32 [%0], {%1, %2};"
                 :: "l"(&d_pool[g * 64 + j0]), "f"(o0), "f"(o1) : "memory");
    if (lane == 0) atomicAdd(&d_gcnt[g], 1.f);
}

// ---------------- head MLP ----------------
__global__ void head_kernel(const float* __restrict__ u,
                            const float* __restrict__ Wl, const float* __restrict__ bl,
                            const float* __restrict__ Wh, const float* __restrict__ bh,
                            float* __restrict__ out) {
    int g = blockIdx.x;
    int j = threadIdx.x;  // 32 threads
    __shared__ float pin[64];
    __shared__ float z[32];
    float cnt = fmaxf(d_gcnt[g], 1.f);
    for (int k = j; k < 64; k += 32) pin[k] = d_pool[g * 64 + k] / cnt;
    __syncthreads();
    float a = __ldg(&bl[j]);
#pragma unroll 8
    for (int k = 0; k < 64; k++) a += pin[k] * __ldg(&Wl[j * 65 + k]);
    a += __ldg(&u[g]) * __ldg(&Wl[j * 65 + 64]);
    z[j] = fmaxf(a, 0.f);
    __syncthreads();
    if (j < 10) {
        float o = __ldg(&bh[j]);
#pragma unroll
        for (int k = 0; k < 32; k++) o += z[k] * __ldg(&Wh[j * 32 + k]);
        out[g * 10 + j] = o;
    }
}

// ---------------- launch ----------------
extern "C" void kernel_launch(void* const* d_in, const int* in_sizes, int n_in,
                              void* d_out, int out_size) {
    const float* x     = (const float*)d_in[0];
    const int*   ei    = (const int*)d_in[1];
    const float* eattr = (const float*)d_in[2];
    const int*   batch = (const int*)d_in[3];
    const float* u     = (const float*)d_in[4];
    const float* Wl1   = (const float*)d_in[5];
    const float* bl1   = (const float*)d_in[6];
    const float* Wr1   = (const float*)d_in[7];
    const float* br1   = (const float*)d_in[8];
    const float* We1   = (const float*)d_in[9];
    const float* att1  = (const float*)d_in[10];
    const float* b1    = (const float*)d_in[11];
    const float* Wl2   = (const float*)d_in[12];
    const float* bl2   = (const float*)d_in[13];
    const float* Wr2   = (const float*)d_in[14];
    const float* br2   = (const float*)d_in[15];
    const float* We2   = (const float*)d_in[16];
    const float* att2  = (const float*)d_in[17];
    const float* b2    = (const float*)d_in[18];
    const float* Wlin  = (const float*)d_in[19];
    const float* blin  = (const float*)d_in[20];
    const float* Wh    = (const float*)d_in[21];
    const float* bh    = (const float*)d_in[22];
    float* out = (float*)d_out;

    float *p_xl1, *p_xr1, *p_h1, *p_xl2, *p_xr2;
    cudaGetSymbolAddress((void**)&p_xl1, d_xl1);
    cudaGetSymbolAddress((void**)&p_xr1, d_xr1);
    cudaGetSymbolAddress((void**)&p_h1,  d_h1);
    cudaGetSymbolAddress((void**)&p_xl2, d_xl2);
    cudaGetSymbolAddress((void**)&p_xr2, d_xr2);

    const int SMEM_G1 = (128 * (128 + 2) + 128 * (16 + 4)) * 4;  // 76800
    const int SMEM_G2 = (128 * (64 + 2) + 128 * (32 + 4)) * 4;   // 52224
    cudaFuncSetAttribute(gemm_xt_kernel<128, 16>, cudaFuncAttributeMaxDynamicSharedMemorySize, SMEM_G1);
    cudaFuncSetAttribute(gemm_xt_kernel<64, 32>,  cudaFuncAttributeMaxDynamicSharedMemorySize, SMEM_G2);

    // ---- CSR build ----
    zero_kernel<<<(NN * 3 + 255) / 256, 256>>>();
    hist_kernel<<<(NE + 255) / 256, 256>>>(ei, eattr);
    scan_part_kernel<<<NSCAN, 256>>>();
    scan_top_kernel<<<1, 64>>>();
    scan_fin_kernel<<<(NN + 255) / 256, 256>>>();
    scatter_kernel<<<(NE + 255) / 256, 256>>>(ei, eattr);

    // ---- layer 1 ----
    gemm_xt_kernel<128, 16><<<(NN + 15) / 16, 256, SMEM_G1>>>(x, Wl1, bl1, p_xl1, NN);
    gemm_xt_kernel<128, 16><<<(NN + 15) / 16, 256, SMEM_G1>>>(x, Wr1, br1, p_xr1, NN);
    gather1_kernel<<<(NN * 32 + 255) / 256, 256>>>(We1, att1, b1);

    // ---- layer 2 ----
    gemm_xt_kernel<64, 32><<<(NN + 31) / 32, 256, SMEM_G2>>>(p_h1, Wl2, bl2, p_xl2, NN);
    gemm_xt_kernel<64, 32><<<(NN + 31) / 32, 256, SMEM_G2>>>(p_h1, Wr2, br2, p_xr2, NN);
    gather2_kernel<<<(NN * 32 + 255) / 256, 256>>>(We2, att2, b2, batch);

    // ---- head ----
    head_kernel<<<NG, 32>>>(u, Wlin, blin, Wh, bh, out);
}

// round 9
// speedup vs baseline: 2.0520x; 1.1378x over previous
#include <cuda_runtime.h>

#define NN 50000
#define NE 800000
#define NT 850000   // NE + NN self loops
#define NG 512
#define SCAN_BLK 1024
#define NSCAN ((NN + SCAN_BLK - 1) / SCAN_BLK)   // 49

// ---------------- scratch (device globals; no allocation allowed) ----------------
__device__ __align__(16) float d_xl1[NN * 128];
__device__ __align__(16) float d_xr1[NN * 128];
__device__ __align__(16) float d_h1[NN * 128];
__device__ __align__(16) float d_xl2[NN * 64];
__device__ __align__(16) float d_xr2[NN * 64];
__device__ __align__(16) float4 d_rec[NT];      // CSR records: {src_as_float, a0, a1, a2}
__device__ __align__(16) float4 d_degattr[NN];  // {cnt_as_float, sum_a0, sum_a1, sum_a2}
__device__ int   d_cnt[NN];                     // real in-degree (finalized int)
__device__ int   d_off[NN];                     // CSR start offset
__device__ int   d_fill[NN];
__device__ int   d_bsum[NSCAN];
__device__ int   d_boff[NSCAN];
__device__ float d_pool[NG * 64];
__device__ float d_gcnt[NG];

__device__ __forceinline__ float lrelu(float m) { return (m > 0.f) ? m : 0.2f * m; }

// ---------------- zero init (graph replays need fresh accumulators) ----------------
__global__ void zero_kernel() {
    int i = blockIdx.x * 256 + threadIdx.x;
    if (i < NN * 4) reinterpret_cast<float*>(d_degattr)[i] = 0.f;
    if (i < NN)     d_fill[i] = 0;
    if (i < NG * 64) d_pool[i] = 0.f;
    if (i < NG)      d_gcnt[i] = 0.f;
}

// ---------------- histogram + self-loop attr sums: ONE vector RED per edge ----------------
__global__ void hist_kernel(const int* __restrict__ ei, const float* __restrict__ ea) {
    int e = blockIdx.x * 256 + threadIdx.x;
    if (e >= NE) return;
    int d = ei[NE + e];
    float a0 = ea[e * 3 + 0], a1 = ea[e * 3 + 1], a2 = ea[e * 3 + 2];
    asm volatile("red.global.add.v4.f32 [%0], {%1, %2, %3, %4};"
                 :: "l"(&d_degattr[d]), "f"(1.0f), "f"(a0), "f"(a1), "f"(a2)
                 : "memory");
}

// ---------------- 2-level exclusive scan of (cnt[v]+1) ----------------
__global__ void scan_part_kernel() {
    __shared__ int wsum[8];
    __shared__ int woff[8];
    int b = blockIdx.x, t = threadIdx.x;
    int lane = t & 31, wid = t >> 5;
    int base = b * SCAN_BLK + t * 4;
    int v0 = (base + 0 < NN) ? (int)d_degattr[base + 0].x + 1 : 0;
    int v1 = (base + 1 < NN) ? (int)d_degattr[base + 1].x + 1 : 0;
    int v2 = (base + 2 < NN) ? (int)d_degattr[base + 2].x + 1 : 0;
    int v3 = (base + 3 < NN) ? (int)d_degattr[base + 3].x + 1 : 0;
    int tsum = v0 + v1 + v2 + v3;
    int x = tsum;
#pragma unroll
    for (int o = 1; o < 32; o <<= 1) {
        int y = __shfl_up_sync(0xffffffffu, x, o);
        if (lane >= o) x += y;
    }
    if (lane == 31) wsum[wid] = x;
    __syncthreads();
    if (t == 0) {
        int r = 0;
#pragma unroll
        for (int i = 0; i < 8; i++) { woff[i] = r; r += wsum[i]; }
        d_bsum[b] = r;
    }
    __syncthreads();
    int excl = x - tsum + woff[wid];
    if (base + 0 < NN) d_off[base + 0] = excl;
    if (base + 1 < NN) d_off[base + 1] = excl + v0;
    if (base + 2 < NN) d_off[base + 2] = excl + v0 + v1;
    if (base + 3 < NN) d_off[base + 3] = excl + v0 + v1 + v2;
}

__global__ void scan_top_kernel() {
    __shared__ int s[NSCAN];
    int t = threadIdx.x;
    if (t < NSCAN) s[t] = d_bsum[t];
    __syncthreads();
    if (t == 0) {
        int r = 0;
        for (int i = 0; i < NSCAN; i++) { int v = s[i]; s[i] = r; r += v; }
    }
    __syncthreads();
    if (t < NSCAN) d_boff[t] = s[t];
}

// finalize offsets + degree + write the self-loop record (mean of incoming edge attrs)
__global__ void scan_fin_kernel() {
    int v = blockIdx.x * 256 + threadIdx.x;
    if (v >= NN) return;
    int off = d_off[v] + d_boff[v >> 10];
    d_off[v] = off;
    float4 da = d_degattr[v];
    int c = (int)da.x;
    d_cnt[v] = c;
    float cf = fmaxf(da.x, 1.f);
    float4 r;
    r.x = __int_as_float(v);
    r.y = da.y / cf;
    r.z = da.z / cf;
    r.w = da.w / cf;
    d_rec[off + c] = r;   // self loop goes last
}

// scatter real edges into CSR
__global__ void scatter_kernel(const int* __restrict__ ei, const float* __restrict__ ea) {
    int e = blockIdx.x * 256 + threadIdx.x;
    if (e >= NE) return;
    int s = ei[e], d = ei[NE + e];
    int slot = d_off[d] + atomicAdd(&d_fill[d], 1);
    float4 r;
    r.x = __int_as_float(s);
    r.y = ea[e * 3 + 0];
    r.z = ea[e * 3 + 1];
    r.w = ea[e * 3 + 2];
    d_rec[slot] = r;
}

// ---------------- dual node transform: Ya = X@Wa^T+ba, Yb = X@Wb^T+bb ----------------
// 256 threads. X tile loaded ONCE to smem; W plane swapped between two compute phases.
// Thread computes 4 outputs x 4 nodes: per k, 2x LDS.128 + 16 FFMA (~89% FFMA density).
template<int M, int TILE>
__global__ __launch_bounds__(256, 2)
void gemm_dual_kernel(const float* __restrict__ X,
                      const float* __restrict__ Wa, const float* __restrict__ ba,
                      const float* __restrict__ Wb, const float* __restrict__ bb,
                      float* __restrict__ Ya, float* __restrict__ Yb, int n) {
    extern __shared__ float sm[];
    float* Ws = sm;                          // [128][M+4]
    float* Xs = sm + 128 * (M + 4);          // [128][TILE+4]
    const int tid = threadIdx.x;
    const int base = blockIdx.x * TILE;

    for (int idx = tid; idx < TILE * 128; idx += 256) {
        int t = idx >> 7, k = idx & 127;
        int node = base + t;
        Xs[k * (TILE + 4) + t] = (node < n) ? X[node * 128 + k] : 0.f;
    }

    const int JG = M / 4;
    const int j0 = (tid % JG) * 4;
    const int t0 = (tid / JG) * 4;

    const float* Wp = Wa;
    const float* bp = ba;
    float* Yp = Ya;

#pragma unroll
    for (int rep = 0; rep < 2; rep++) {
        __syncthreads();   // Xs ready (rep 0) / previous compute done reading Ws (rep 1)
        for (int idx = tid; idx < M * 128; idx += 256) {
            int j = idx >> 7, k = idx & 127;
            Ws[k * (M + 4) + j] = Wp[idx];
        }
        __syncthreads();

        float acc[4][4];
#pragma unroll
        for (int a = 0; a < 4; a++)
#pragma unroll
            for (int b = 0; b < 4; b++) acc[a][b] = 0.f;

#pragma unroll 4
        for (int k = 0; k < 128; k++) {
            float4 wv = *reinterpret_cast<const float4*>(&Ws[k * (M + 4) + j0]);
            float4 xv = *reinterpret_cast<const float4*>(&Xs[k * (TILE + 4) + t0]);
            acc[0][0] += xv.x * wv.x; acc[0][1] += xv.x * wv.y; acc[0][2] += xv.x * wv.z; acc[0][3] += xv.x * wv.w;
            acc[1][0] += xv.y * wv.x; acc[1][1] += xv.y * wv.y; acc[1][2] += xv.y * wv.z; acc[1][3] += xv.y * wv.w;
            acc[2][0] += xv.z * wv.x; acc[2][1] += xv.z * wv.y; acc[2][2] += xv.z * wv.z; acc[2][3] += xv.z * wv.w;
            acc[3][0] += xv.w * wv.x; acc[3][1] += xv.w * wv.y; acc[3][2] += xv.w * wv.z; acc[3][3] += xv.w * wv.w;
        }

        float4 bv = *reinterpret_cast<const float4*>(&bp[j0]);
#pragma unroll
        for (int t = 0; t < 4; t++) {
            int node = base + t0 + t;
            if (node < n) {
                float4 o;
                o.x = acc[t][0] + bv.x; o.y = acc[t][1] + bv.y;
                o.z = acc[t][2] + bv.z; o.w = acc[t][3] + bv.w;
                *reinterpret_cast<float4*>(&Yp[node * M + j0]) = o;
            }
        }
        Wp = Wb; bp = bb; Yp = Yb;
    }
}

// ---------------- layer 1 gather: warp per dst node, fully fused ----------------
__global__ void gather1_kernel(const float* __restrict__ We, const float* __restrict__ att,
                               const float* __restrict__ b1) {
    __shared__ float sWe[128 * 3];
    __shared__ __align__(16) float sAtt[128];
    __shared__ __align__(16) float sB[128];
    int tid = threadIdx.x;
    for (int i = tid; i < 384; i += 256) sWe[i] = We[i];
    for (int i = tid; i < 128; i += 256) { sAtt[i] = att[i]; sB[i] = b1[i]; }
    __syncthreads();

    int v = (blockIdx.x * 256 + tid) >> 5;
    if (v >= NN) return;
    int lane = tid & 31;
    int j0 = lane * 4;

    float4 xr = *reinterpret_cast<const float4*>(&d_xr1[v * 128 + j0]);
    float4 at = *reinterpret_cast<const float4*>(&sAtt[j0]);
    float w0 = sWe[j0*3+0], w1 = sWe[j0*3+1], w2 = sWe[j0*3+2];
    float w3 = sWe[j0*3+3], w4 = sWe[j0*3+4], w5 = sWe[j0*3+5];
    float w6 = sWe[j0*3+6], w7 = sWe[j0*3+7], w8 = sWe[j0*3+8];
    float w9 = sWe[j0*3+9], wa = sWe[j0*3+10], wb = sWe[j0*3+11];

    int off = d_off[v];
    int deg = d_cnt[v] + 1;

    float a0 = 0.f, a1 = 0.f, a2 = 0.f, a3 = 0.f, den = 0.f;
    float4 rec = __ldg(&d_rec[off]);
    for (int i = 0; i < deg; i++) {
        int s = __float_as_int(rec.x);
        float ea0 = rec.y, ea1 = rec.z, ea2 = rec.w;
        if (i + 1 < deg) rec = __ldg(&d_rec[off + i + 1]);   // prefetch next
        float4 xl = *reinterpret_cast<const float4*>(&d_xl1[s * 128 + j0]);
        float m0 = lrelu(xl.x + xr.x + w0 * ea0 + w1 * ea1 + w2 * ea2);
        float m1 = lrelu(xl.y + xr.y + w3 * ea0 + w4 * ea1 + w5 * ea2);
        float m2 = lrelu(xl.z + xr.z + w6 * ea0 + w7 * ea1 + w8 * ea2);
        float m3 = lrelu(xl.w + xr.w + w9 * ea0 + wa * ea1 + wb * ea2);
        float p = m0 * at.x + m1 * at.y + m2 * at.z + m3 * at.w;
        p += __shfl_xor_sync(0xffffffffu, p, 1);
        p += __shfl_xor_sync(0xffffffffu, p, 2);
        p += __shfl_xor_sync(0xffffffffu, p, 4);
        float w = __expf(p);
        den += w;
        a0 += w * xl.x; a1 += w * xl.y; a2 += w * xl.z; a3 += w * xl.w;
    }
    float inv = 1.f / den;
    float4 bv = *reinterpret_cast<const float4*>(&sB[j0]);
    float o0 = a0 * inv + bv.x, o1 = a1 * inv + bv.y;
    float o2 = a2 * inv + bv.z, o3 = a3 * inv + bv.w;
    float4 o;
    o.x = (o0 > 0.f) ? o0 : (__expf(o0) - 1.f);
    o.y = (o1 > 0.f) ? o1 : (__expf(o1) - 1.f);
    o.z = (o2 > 0.f) ? o2 : (__expf(o2) - 1.f);
    o.w = (o3 > 0.f) ? o3 : (__expf(o3) - 1.f);
    *reinterpret_cast<float4*>(&d_h1[v * 128 + j0]) = o;
}

// ---------------- layer 2 gather: warp per dst node + pooled accumulation ----------------
__global__ void gather2_kernel(const float* __restrict__ We, const float* __restrict__ att,
                               const float* __restrict__ b2, const int* __restrict__ batch) {
    __shared__ float sWe[64 * 3];
    __shared__ __align__(8) float sAtt[64];
    __shared__ __align__(8) float sB[64];
    int tid = threadIdx.x;
    for (int i = tid; i < 192; i += 256) sWe[i] = We[i];
    for (int i = tid; i < 64; i += 256) { sAtt[i] = att[i]; sB[i] = b2[i]; }
    __syncthreads();

    int v = (blockIdx.x * 256 + tid) >> 5;
    if (v >= NN) return;
    int lane = tid & 31;
    int j0 = lane * 2;

    float2 xr = *reinterpret_cast<const float2*>(&d_xr2[v * 64 + j0]);
    float2 at = *reinterpret_cast<const float2*>(&sAtt[j0]);
    float w0 = sWe[j0*3+0], w1 = sWe[j0*3+1], w2 = sWe[j0*3+2];
    float w3 = sWe[j0*3+3], w4 = sWe[j0*3+4], w5 = sWe[j0*3+5];

    int off = d_off[v];
    int deg = d_cnt[v] + 1;

    float a0 = 0.f, a1 = 0.f, den = 0.f;
    float4 rec = __ldg(&d_rec[off]);
    for (int i = 0; i < deg; i++) {
        int s = __float_as_int(rec.x);
        float ea0 = rec.y, ea1 = rec.z, ea2 = rec.w;
        if (i + 1 < deg) rec = __ldg(&d_rec[off + i + 1]);
        float2 xl = *reinterpret_cast<const float2*>(&d_xl2[s * 64 + j0]);
        float m0 = lrelu(xl.x + xr.x + w0 * ea0 + w1 * ea1 + w2 * ea2);
        float m1 = lrelu(xl.y + xr.y + w3 * ea0 + w4 * ea1 + w5 * ea2);
        float p = m0 * at.x + m1 * at.y;
#pragma unroll
        for (int o = 16; o > 0; o >>= 1) p += __shfl_xor_sync(0xffffffffu, p, o);
        float w = __expf(p);
        den += w;
        a0 += w * xl.x; a1 += w * xl.y;
    }
    float inv = 1.f / den;
    float o0 = a0 * inv + sB[j0], o1 = a1 * inv + sB[j0 + 1];
    o0 = (o0 > 0.f) ? o0 : (__expf(o0) - 1.f);
    o1 = (o1 > 0.f) ? o1 : (__expf(o1) - 1.f);
    int g = __ldg(&batch[v]);
    asm volatile("red.global.add.v2.f32 [%0], {%1, %2};"
                 :: "l"(&d_pool[g * 64 + j0]), "f"(o0), "f"(o1) : "memory");
    if (lane == 0) atomicAdd(&d_gcnt[g], 1.f);
}

// ---------------- head MLP ----------------
__global__ void head_kernel(const float* __restrict__ u,
                            const float* __restrict__ Wl, const float* __restrict__ bl,
                            const float* __restrict__ Wh, const float* __restrict__ bh,
                            float* __restrict__ out) {
    int g = blockIdx.x;
    int j = threadIdx.x;  // 32 threads
    __shared__ float pin[64];
    __shared__ float z[32];
    float cnt = fmaxf(d_gcnt[g], 1.f);
    for (int k = j; k < 64; k += 32) pin[k] = d_pool[g * 64 + k] / cnt;
    __syncthreads();
    float a = __ldg(&bl[j]);
#pragma unroll 8
    for (int k = 0; k < 64; k++) a += pin[k] * __ldg(&Wl[j * 65 + k]);
    a += __ldg(&u[g]) * __ldg(&Wl[j * 65 + 64]);
    z[j] = fmaxf(a, 0.f);
    __syncthreads();
    if (j < 10) {
        float o = __ldg(&bh[j]);
#pragma unroll
        for (int k = 0; k < 32; k++) o += z[k] * __ldg(&Wh[j * 32 + k]);
        out[g * 10 + j] = o;
    }
}

// ---------------- launch ----------------
extern "C" void kernel_launch(void* const* d_in, const int* in_sizes, int n_in,
                              void* d_out, int out_size) {
    const float* x     = (const float*)d_in[0];
    const int*   ei    = (const int*)d_in[1];
    const float* eattr = (const float*)d_in[2];
    const int*   batch = (const int*)d_in[3];
    const float* u     = (const float*)d_in[4];
    const float* Wl1   = (const float*)d_in[5];
    const float* bl1   = (const float*)d_in[6];
    const float* Wr1   = (const float*)d_in[7];
    const float* br1   = (const float*)d_in[8];
    const float* We1   = (const float*)d_in[9];
    const float* att1  = (const float*)d_in[10];
    const float* b1    = (const float*)d_in[11];
    const float* Wl2   = (const float*)d_in[12];
    const float* bl2   = (const float*)d_in[13];
    const float* Wr2   = (const float*)d_in[14];
    const float* br2   = (const float*)d_in[15];
    const float* We2   = (const float*)d_in[16];
    const float* att2  = (const float*)d_in[17];
    const float* b2    = (const float*)d_in[18];
    const float* Wlin  = (const float*)d_in[19];
    const float* blin  = (const float*)d_in[20];
    const float* Wh    = (const float*)d_in[21];
    const float* bh    = (const float*)d_in[22];
    float* out = (float*)d_out;

    float *p_xl1, *p_xr1, *p_h1, *p_xl2, *p_xr2;
    cudaGetSymbolAddress((void**)&p_xl1, d_xl1);
    cudaGetSymbolAddress((void**)&p_xr1, d_xr1);
    cudaGetSymbolAddress((void**)&p_h1,  d_h1);
    cudaGetSymbolAddress((void**)&p_xl2, d_xl2);
    cudaGetSymbolAddress((void**)&p_xr2, d_xr2);

    const int SMEM_G1 = (128 * (128 + 4) + 128 * (32 + 4)) * 4;  // 86016
    const int SMEM_G2 = (128 * (64 + 4) + 128 * (64 + 4)) * 4;   // 69632
    cudaFuncSetAttribute(gemm_dual_kernel<128, 32>, cudaFuncAttributeMaxDynamicSharedMemorySize, SMEM_G1);
    cudaFuncSetAttribute(gemm_dual_kernel<64, 64>,  cudaFuncAttributeMaxDynamicSharedMemorySize, SMEM_G2);

    // ---- CSR build ----
    zero_kernel<<<(NN * 4 + 255) / 256, 256>>>();
    hist_kernel<<<(NE + 255) / 256, 256>>>(ei, eattr);
    scan_part_kernel<<<NSCAN, 256>>>();
    scan_top_kernel<<<1, 64>>>();
    scan_fin_kernel<<<(NN + 255) / 256, 256>>>();
    scatter_kernel<<<(NE + 255) / 256, 256>>>(ei, eattr);

    // ---- layer 1 ----
    gemm_dual_kernel<128, 32><<<(NN + 31) / 32, 256, SMEM_G1>>>(x, Wl1, bl1, Wr1, br1, p_xl1, p_xr1, NN);
    gather1_kernel<<<(NN * 32 + 255) / 256, 256>>>(We1, att1, b1);

    // ---- layer 2 ----
    gemm_dual_kernel<64, 64><<<(NN + 63) / 64, 256, SMEM_G2>>>(p_h1, Wl2, bl2, Wr2, br2, p_xl2, p_xr2, NN);
    gather2_kernel<<<(NN * 32 + 255) / 256, 256>>>(We2, att2, b2, batch);

    // ---- head ----
    head_kernel<<<NG, 32>>>(u, Wlin, blin, Wh, bh, out);
}

// round 10
// speedup vs baseline: 2.1612x; 1.0532x over previous
#include <cuda_runtime.h>

#define NN 50000
#define NE 800000
#define NT 850000
#define NG 512
#define SCAN_BLK 1024
#define NSCAN ((NN + SCAN_BLK - 1) / SCAN_BLK)   // 49

// W pack offsets (elements) in d_whi/d_wlo
#define WOFF_L1 0
#define WOFF_R1 16384
#define WOFF_L2 32768
#define WOFF_R2 40960
#define WTOT    49152

// ---------------- scratch (device globals; no allocation allowed) ----------------
__device__ __align__(16) float d_xl1[NN * 128];
__device__ __align__(16) float d_xr1[NN * 128];
__device__ __align__(16) float d_h1[NN * 128];
__device__ __align__(16) float d_xl2[NN * 64];
__device__ __align__(16) float d_xr2[NN * 64];
__device__ __align__(16) float d_xhi[NN * 128];
__device__ __align__(16) float d_xlo[NN * 128];
__device__ __align__(16) float d_whi[WTOT];
__device__ __align__(16) float d_wlo[WTOT];
__device__ __align__(16) float4 d_rec[NT];      // CSR records: {src_as_float, a0, a1, a2}
__device__ __align__(16) float4 d_degattr[NN];  // {cnt_as_float, sum_a0, sum_a1, sum_a2}
__device__ int   d_off[NN];                     // CSR start offset (block-local before boff add)
__device__ int   d_fill[NN];
__device__ int   d_bsum[NSCAN];
__device__ int   d_boff[NSCAN];
__device__ float d_pool[NG * 64];
__device__ float d_gcnt[NG];

__device__ __forceinline__ float lrelu(float m) { return (m > 0.f) ? m : 0.2f * m; }

__device__ __forceinline__ void tf32split(float v, float& hi, float& lo) {
    unsigned hb; asm("cvt.rna.tf32.f32 %0, %1;" : "=r"(hb) : "f"(v));
    hi = __uint_as_float(hb);
    float l = v - hi;
    unsigned lb; asm("cvt.rna.tf32.f32 %0, %1;" : "=r"(lb) : "f"(l));
    lo = __uint_as_float(lb);
}

__device__ __forceinline__ void mma_tf32(float* c,
                                         unsigned a0, unsigned a1, unsigned a2, unsigned a3,
                                         unsigned b0, unsigned b1) {
    asm volatile("mma.sync.aligned.m16n8k8.row.col.f32.tf32.tf32.f32 "
                 "{%0,%1,%2,%3}, {%4,%5,%6,%7}, {%8,%9}, {%0,%1,%2,%3};"
                 : "+f"(c[0]), "+f"(c[1]), "+f"(c[2]), "+f"(c[3])
                 : "r"(a0), "r"(a1), "r"(a2), "r"(a3), "r"(b0), "r"(b1));
}

// ---------------- zero init ----------------
__global__ void zero_kernel() {
    int i = blockIdx.x * 256 + threadIdx.x;
    if (i < NN * 4) reinterpret_cast<float*>(d_degattr)[i] = 0.f;
    if (i < NN)     d_fill[i] = 0;
    if (i < NG * 64) d_pool[i] = 0.f;
    if (i < NG)      d_gcnt[i] = 0.f;
}

// ---------------- histogram + self-loop attr sums: one vector RED per edge ----------------
__global__ void hist_kernel(const int* __restrict__ ei, const float* __restrict__ ea) {
    int e = blockIdx.x * 256 + threadIdx.x;
    if (e >= NE) return;
    int d = ei[NE + e];
    float a0 = ea[e * 3 + 0], a1 = ea[e * 3 + 1], a2 = ea[e * 3 + 2];
    asm volatile("red.global.add.v4.f32 [%0], {%1, %2, %3, %4};"
                 :: "l"(&d_degattr[d]), "f"(1.0f), "f"(a0), "f"(a1), "f"(a2)
                 : "memory");
}

// ---------------- 2-level exclusive scan of cnt[v] ----------------
__global__ void scan_part_kernel() {
    __shared__ int wsum[8];
    __shared__ int woff[8];
    int b = blockIdx.x, t = threadIdx.x;
    int lane = t & 31, wid = t >> 5;
    int base = b * SCAN_BLK + t * 4;
    int v0 = (base + 0 < NN) ? (int)d_degattr[base + 0].x : 0;
    int v1 = (base + 1 < NN) ? (int)d_degattr[base + 1].x : 0;
    int v2 = (base + 2 < NN) ? (int)d_degattr[base + 2].x : 0;
    int v3 = (base + 3 < NN) ? (int)d_degattr[base + 3].x : 0;
    int tsum = v0 + v1 + v2 + v3;
    int x = tsum;
#pragma unroll
    for (int o = 1; o < 32; o <<= 1) {
        int y = __shfl_up_sync(0xffffffffu, x, o);
        if (lane >= o) x += y;
    }
    if (lane == 31) wsum[wid] = x;
    __syncthreads();
    if (t == 0) {
        int r = 0;
#pragma unroll
        for (int i = 0; i < 8; i++) { woff[i] = r; r += wsum[i]; }
        d_bsum[b] = r;
    }
    __syncthreads();
    int excl = x - tsum + woff[wid];
    if (base + 0 < NN) d_off[base + 0] = excl;
    if (base + 1 < NN) d_off[base + 1] = excl + v0;
    if (base + 2 < NN) d_off[base + 2] = excl + v0 + v1;
    if (base + 3 < NN) d_off[base + 3] = excl + v0 + v1 + v2;
}

__global__ void scan_top_kernel() {
    __shared__ int s[NSCAN];
    int t = threadIdx.x;
    if (t < NSCAN) s[t] = d_bsum[t];
    __syncthreads();
    if (t == 0) {
        int r = 0;
        for (int i = 0; i < NSCAN; i++) { int v = s[i]; s[i] = r; r += v; }
    }
    __syncthreads();
    if (t < NSCAN) d_boff[t] = s[t];
}

// scatter real edges into CSR (final offset computed inline)
__global__ void scatter_kernel(const int* __restrict__ ei, const float* __restrict__ ea) {
    int e = blockIdx.x * 256 + threadIdx.x;
    if (e >= NE) return;
    int s = ei[e], d = ei[NE + e];
    int slot = d_off[d] + d_boff[d >> 10] + atomicAdd(&d_fill[d], 1);
    float4 r;
    r.x = __int_as_float(s);
    r.y = ea[e * 3 + 0];
    r.z = ea[e * 3 + 1];
    r.w = ea[e * 3 + 2];
    d_rec[slot] = r;
}

// ---------------- tf32 hi/lo splits ----------------
__global__ void split_w_kernel(const float* __restrict__ Wl1, const float* __restrict__ Wr1,
                               const float* __restrict__ Wl2, const float* __restrict__ Wr2) {
    int i = blockIdx.x * 256 + threadIdx.x;
    if (i >= WTOT) return;
    float v;
    if (i < WOFF_R1)      v = Wl1[i];
    else if (i < WOFF_L2) v = Wr1[i - WOFF_R1];
    else if (i < WOFF_R2) v = Wl2[i - WOFF_L2];
    else                  v = Wr2[i - WOFF_R2];
    float hi, lo; tf32split(v, hi, lo);
    d_whi[i] = hi; d_wlo[i] = lo;
}

__global__ void split_x_kernel(const float* __restrict__ X, int n) {
    int i = blockIdx.x * 256 + threadIdx.x;
    if (i >= n) return;
    float hi, lo; tf32split(X[i], hi, lo);
    d_xhi[i] = hi; d_xlo[i] = lo;
}

// ---------------- tf32 tensor-core dual GEMM: Ya = X@Wa^T+ba, Yb = X@Wb^T+bb ----------------
// K = 128. Block 256 thr (8 warps); block tile 128 nodes x M. Warp tile 16 nodes x M.
// 3xTF32: acc += Al*Bh + Ah*Bl + Ah*Bh  (near-fp32 accuracy).
template<int M>
__global__ __launch_bounds__(256, 2)
void gemm_tf32_dual_kernel(const float* __restrict__ ba, const float* __restrict__ bb,
                           int wOffA, int wOffB,
                           float* __restrict__ Ya, float* __restrict__ Yb) {
    const int KP = 20;                         // padded k-stride (conflict-free)
    __shared__ float sXh[128 * KP], sXl[128 * KP];
    __shared__ float sWh[M * KP],   sWl[M * KP];
    const int tid = threadIdx.x;
    const int warp = tid >> 5, lane = tid & 31;
    const int g = lane >> 2, tig = lane & 3;
    const int base = blockIdx.x * 128;
    const int NTILE = M / 8;

#pragma unroll
    for (int phase = 0; phase < 2; phase++) {
        const float* Wh_ = d_whi + (phase ? wOffB : wOffA);
        const float* Wl_ = d_wlo + (phase ? wOffB : wOffA);
        const float* bp  = phase ? bb : ba;
        float* Yp        = phase ? Yb : Ya;

        float acc[NTILE][4];
#pragma unroll
        for (int nt = 0; nt < NTILE; nt++)
#pragma unroll
            for (int q = 0; q < 4; q++) acc[nt][q] = 0.f;

        for (int kc = 0; kc < 8; kc++) {
            __syncthreads();
            // stage X chunk [128 nodes x 16 k], hi+lo
            for (int i = tid; i < 512; i += 256) {
                int row = i >> 2, c4 = (i & 3) * 4;
                int node = base + row;
                float4 vh = make_float4(0.f, 0.f, 0.f, 0.f), vl = vh;
                if (node < NN) {
                    vh = *reinterpret_cast<const float4*>(&d_xhi[node * 128 + kc * 16 + c4]);
                    vl = *reinterpret_cast<const float4*>(&d_xlo[node * 128 + kc * 16 + c4]);
                }
                *reinterpret_cast<float4*>(&sXh[row * KP + c4]) = vh;
                *reinterpret_cast<float4*>(&sXl[row * KP + c4]) = vl;
            }
            // stage W chunk [M x 16 k], hi+lo
            for (int i = tid; i < M * 4; i += 256) {
                int row = i >> 2, c4 = (i & 3) * 4;
                *reinterpret_cast<float4*>(&sWh[row * KP + c4]) =
                    *reinterpret_cast<const float4*>(&Wh_[row * 128 + kc * 16 + c4]);
                *reinterpret_cast<float4*>(&sWl[row * KP + c4]) =
                    *reinterpret_cast<const float4*>(&Wl_[row * 128 + kc * 16 + c4]);
            }
            __syncthreads();

#pragma unroll
            for (int ks = 0; ks < 2; ks++) {
                int k0 = ks * 8;
                int ar = warp * 16 + g;
                unsigned ah0 = __float_as_uint(sXh[ar * KP + k0 + tig]);
                unsigned ah1 = __float_as_uint(sXh[(ar + 8) * KP + k0 + tig]);
                unsigned ah2 = __float_as_uint(sXh[ar * KP + k0 + tig + 4]);
                unsigned ah3 = __float_as_uint(sXh[(ar + 8) * KP + k0 + tig + 4]);
                unsigned al0 = __float_as_uint(sXl[ar * KP + k0 + tig]);
                unsigned al1 = __float_as_uint(sXl[(ar + 8) * KP + k0 + tig]);
                unsigned al2 = __float_as_uint(sXl[ar * KP + k0 + tig + 4]);
                unsigned al3 = __float_as_uint(sXl[(ar + 8) * KP + k0 + tig + 4]);
#pragma unroll
                for (int nt = 0; nt < NTILE; nt++) {
                    int bn = nt * 8 + g;
                    unsigned bh0 = __float_as_uint(sWh[bn * KP + k0 + tig]);
                    unsigned bh1 = __float_as_uint(sWh[bn * KP + k0 + tig + 4]);
                    unsigned bl0 = __float_as_uint(sWl[bn * KP + k0 + tig]);
                    unsigned bl1 = __float_as_uint(sWl[bn * KP + k0 + tig + 4]);
                    mma_tf32(acc[nt], al0, al1, al2, al3, bh0, bh1);  // Al*Bh
                    mma_tf32(acc[nt], ah0, ah1, ah2, ah3, bl0, bl1);  // Ah*Bl
                    mma_tf32(acc[nt], ah0, ah1, ah2, ah3, bh0, bh1);  // Ah*Bh
                }
            }
        }

        // store with bias
        int r0 = base + warp * 16 + g;
#pragma unroll
        for (int nt = 0; nt < NTILE; nt++) {
            int col = nt * 8 + tig * 2;
            float bx = __ldg(&bp[col]), by = __ldg(&bp[col + 1]);
            if (r0 < NN) {
                float2 o; o.x = acc[nt][0] + bx; o.y = acc[nt][1] + by;
                *reinterpret_cast<float2*>(&Yp[r0 * M + col]) = o;
            }
            if (r0 + 8 < NN) {
                float2 o; o.x = acc[nt][2] + bx; o.y = acc[nt][3] + by;
                *reinterpret_cast<float2*>(&Yp[(r0 + 8) * M + col]) = o;
            }
        }
        __syncthreads();   // protect smem before next phase restage
    }
}

// ---------------- layer 1 gather: warp per dst node, fully fused, self-loop inline ----------------
__global__ void gather1_kernel(const float* __restrict__ We, const float* __restrict__ att,
                               const float* __restrict__ b1) {
    __shared__ float sWe[128 * 3];
    __shared__ __align__(16) float sAtt[128];
    __shared__ __align__(16) float sB[128];
    int tid = threadIdx.x;
    for (int i = tid; i < 384; i += 256) sWe[i] = We[i];
    for (int i = tid; i < 128; i += 256) { sAtt[i] = att[i]; sB[i] = b1[i]; }
    __syncthreads();

    int v = (blockIdx.x * 256 + tid) >> 5;
    if (v >= NN) return;
    int lane = tid & 31;
    int j0 = lane * 4;

    float4 xr = *reinterpret_cast<const float4*>(&d_xr1[v * 128 + j0]);
    float4 at = *reinterpret_cast<const float4*>(&sAtt[j0]);
    float w0 = sWe[j0*3+0], w1 = sWe[j0*3+1], w2 = sWe[j0*3+2];
    float w3 = sWe[j0*3+3], w4 = sWe[j0*3+4], w5 = sWe[j0*3+5];
    float w6 = sWe[j0*3+6], w7 = sWe[j0*3+7], w8 = sWe[j0*3+8];
    float w9 = sWe[j0*3+9], wa = sWe[j0*3+10], wb = sWe[j0*3+11];

    int off = d_off[v] + d_boff[v >> 10];
    float4 da = d_degattr[v];
    int deg = (int)da.x;

    float a0 = 0.f, a1 = 0.f, a2 = 0.f, a3 = 0.f, den = 0.f;
    float4 rec = __ldg(&d_rec[off]);
    for (int i = 0; i < deg; i++) {
        int s = __float_as_int(rec.x);
        float ea0 = rec.y, ea1 = rec.z, ea2 = rec.w;
        if (i + 1 < deg) rec = __ldg(&d_rec[off + i + 1]);
        float4 xl = *reinterpret_cast<const float4*>(&d_xl1[s * 128 + j0]);
        float m0 = lrelu(xl.x + xr.x + w0 * ea0 + w1 * ea1 + w2 * ea2);
        float m1 = lrelu(xl.y + xr.y + w3 * ea0 + w4 * ea1 + w5 * ea2);
        float m2 = lrelu(xl.z + xr.z + w6 * ea0 + w7 * ea1 + w8 * ea2);
        float m3 = lrelu(xl.w + xr.w + w9 * ea0 + wa * ea1 + wb * ea2);
        float p = m0 * at.x + m1 * at.y + m2 * at.z + m3 * at.w;
        p += __shfl_xor_sync(0xffffffffu, p, 1);
        p += __shfl_xor_sync(0xffffffffu, p, 2);
        p += __shfl_xor_sync(0xffffffffu, p, 4);
        float w = __expf(p);
        den += w;
        a0 += w * xl.x; a1 += w * xl.y; a2 += w * xl.z; a3 += w * xl.w;
    }
    {   // self loop: src = v, attrs = mean of incoming
        float cf = fmaxf(da.x, 1.f);
        float ea0 = da.y / cf, ea1 = da.z / cf, ea2 = da.w / cf;
        float4 xl = *reinterpret_cast<const float4*>(&d_xl1[v * 128 + j0]);
        float m0 = lrelu(xl.x + xr.x + w0 * ea0 + w1 * ea1 + w2 * ea2);
        float m1 = lrelu(xl.y + xr.y + w3 * ea0 + w4 * ea1 + w5 * ea2);
        float m2 = lrelu(xl.z + xr.z + w6 * ea0 + w7 * ea1 + w8 * ea2);
        float m3 = lrelu(xl.w + xr.w + w9 * ea0 + wa * ea1 + wb * ea2);
        float p = m0 * at.x + m1 * at.y + m2 * at.z + m3 * at.w;
        p += __shfl_xor_sync(0xffffffffu, p, 1);
        p += __shfl_xor_sync(0xffffffffu, p, 2);
        p += __shfl_xor_sync(0xffffffffu, p, 4);
        float w = __expf(p);
        den += w;
        a0 += w * xl.x; a1 += w * xl.y; a2 += w * xl.z; a3 += w * xl.w;
    }
    float inv = 1.f / den;
    float4 bv = *reinterpret_cast<const float4*>(&sB[j0]);
    float o0 = a0 * inv + bv.x, o1 = a1 * inv + bv.y;
    float o2 = a2 * inv + bv.z, o3 = a3 * inv + bv.w;
    float4 o;
    o.x = (o0 > 0.f) ? o0 : (__expf(o0) - 1.f);
    o.y = (o1 > 0.f) ? o1 : (__expf(o1) - 1.f);
    o.z = (o2 > 0.f) ? o2 : (__expf(o2) - 1.f);
    o.w = (o3 > 0.f) ? o3 : (__expf(o3) - 1.f);
    *reinterpret_cast<float4*>(&d_h1[v * 128 + j0]) = o;
}

// ---------------- layer 2 gather + pooled accumulation ----------------
__global__ void gather2_kernel(const float* __restrict__ We, const float* __restrict__ att,
                               const float* __restrict__ b2, const int* __restrict__ batch) {
    __shared__ float sWe[64 * 3];
    __shared__ __align__(8) float sAtt[64];
    __shared__ __align__(8) float sB[64];
    int tid = threadIdx.x;
    for (int i = tid; i < 192; i += 256) sWe[i] = We[i];
    for (int i = tid; i < 64; i += 256) { sAtt[i] = att[i]; sB[i] = b2[i]; }
    __syncthreads();

    int v = (blockIdx.x * 256 + tid) >> 5;
    if (v >= NN) return;
    int lane = tid & 31;
    int j0 = lane * 2;

    float2 xr = *reinterpret_cast<const float2*>(&d_xr2[v * 64 + j0]);
    float2 at = *reinterpret_cast<const float2*>(&sAtt[j0]);
    float w0 = sWe[j0*3+0], w1 = sWe[j0*3+1], w2 = sWe[j0*3+2];
    float w3 = sWe[j0*3+3], w4 = sWe[j0*3+4], w5 = sWe[j0*3+5];

    int off = d_off[v] + d_boff[v >> 10];
    float4 da = d_degattr[v];
    int deg = (int)da.x;

    float a0 = 0.f, a1 = 0.f, den = 0.f;
    float4 rec = __ldg(&d_rec[off]);
    for (int i = 0; i < deg; i++) {
        int s = __float_as_int(rec.x);
        float ea0 = rec.y, ea1 = rec.z, ea2 = rec.w;
        if (i + 1 < deg) rec = __ldg(&d_rec[off + i + 1]);
        float2 xl = *reinterpret_cast<const float2*>(&d_xl2[s * 64 + j0]);
        float m0 = lrelu(xl.x + xr.x + w0 * ea0 + w1 * ea1 + w2 * ea2);
        float m1 = lrelu(xl.y + xr.y + w3 * ea0 + w4 * ea1 + w5 * ea2);
        float p = m0 * at.x + m1 * at.y;
#pragma unroll
        for (int o = 16; o > 0; o >>= 1) p += __shfl_xor_sync(0xffffffffu, p, o);
        float w = __expf(p);
        den += w;
        a0 += w * xl.x; a1 += w * xl.y;
    }
    {   // self loop
        float cf = fmaxf(da.x, 1.f);
        float ea0 = da.y / cf, ea1 = da.z / cf, ea2 = da.w / cf;
        float2 xl = *reinterpret_cast<const float2*>(&d_xl2[v * 64 + j0]);
        float m0 = lrelu(xl.x + xr.x + w0 * ea0 + w1 * ea1 + w2 * ea2);
        float m1 = lrelu(xl.y + xr.y + w3 * ea0 + w4 * ea1 + w5 * ea2);
        float p = m0 * at.x + m1 * at.y;
#pragma unroll
        for (int o = 16; o > 0; o >>= 1) p += __shfl_xor_sync(0xffffffffu, p, o);
        float w = __expf(p);
        den += w;
        a0 += w * xl.x; a1 += w * xl.y;
    }
    float inv = 1.f / den;
    float o0 = a0 * inv + sB[j0], o1 = a1 * inv + sB[j0 + 1];
    o0 = (o0 > 0.f) ? o0 : (__expf(o0) - 1.f);
    o1 = (o1 > 0.f) ? o1 : (__expf(o1) - 1.f);
    int g = __ldg(&batch[v]);
    asm volatile("red.global.add.v2.f32 [%0], {%1, %2};"
                 :: "l"(&d_pool[g * 64 + j0]), "f"(o0), "f"(o1) : "memory");
    if (lane == 0) atomicAdd(&d_gcnt[g], 1.f);
}

// ---------------- head MLP ----------------
__global__ void head_kernel(const float* __restrict__ u,
                            const float* __restrict__ Wl, const float* __restrict__ bl,
                            const float* __restrict__ Wh, const float* __restrict__ bh,
                            float* __restrict__ out) {
    int g = blockIdx.x;
    int j = threadIdx.x;  // 32 threads
    __shared__ float pin[64];
    __shared__ float z[32];
    float cnt = fmaxf(d_gcnt[g], 1.f);
    for (int k = j; k < 64; k += 32) pin[k] = d_pool[g * 64 + k] / cnt;
    __syncthreads();
    float a = __ldg(&bl[j]);
#pragma unroll 8
    for (int k = 0; k < 64; k++) a += pin[k] * __ldg(&Wl[j * 65 + k]);
    a += __ldg(&u[g]) * __ldg(&Wl[j * 65 + 64]);
    z[j] = fmaxf(a, 0.f);
    __syncthreads();
    if (j < 10) {
        float o = __ldg(&bh[j]);
#pragma unroll
        for (int k = 0; k < 32; k++) o += z[k] * __ldg(&Wh[j * 32 + k]);
        out[g * 10 + j] = o;
    }
}

// ---------------- launch ----------------
extern "C" void kernel_launch(void* const* d_in, const int* in_sizes, int n_in,
                              void* d_out, int out_size) {
    const float* x     = (const float*)d_in[0];
    const int*   ei    = (const int*)d_in[1];
    const float* eattr = (const float*)d_in[2];
    const int*   batch = (const int*)d_in[3];
    const float* u     = (const float*)d_in[4];
    const float* Wl1   = (const float*)d_in[5];
    const float* bl1   = (const float*)d_in[6];
    const float* Wr1   = (const float*)d_in[7];
    const float* br1   = (const float*)d_in[8];
    const float* We1   = (const float*)d_in[9];
    const float* att1  = (const float*)d_in[10];
    const float* b1    = (const float*)d_in[11];
    const float* Wl2   = (const float*)d_in[12];
    const float* bl2   = (const float*)d_in[13];
    const float* Wr2   = (const float*)d_in[14];
    const float* br2   = (const float*)d_in[15];
    const float* We2   = (const float*)d_in[16];
    const float* att2  = (const float*)d_in[17];
    const float* b2    = (const float*)d_in[18];
    const float* Wlin  = (const float*)d_in[19];
    const float* blin  = (const float*)d_in[20];
    const float* Wh    = (const float*)d_in[21];
    const float* bh    = (const float*)d_in[22];
    float* out = (float*)d_out;

    float *p_xl1, *p_xr1, *p_h1, *p_xl2, *p_xr2;
    cudaGetSymbolAddress((void**)&p_xl1, d_xl1);
    cudaGetSymbolAddress((void**)&p_xr1, d_xr1);
    cudaGetSymbolAddress((void**)&p_h1,  d_h1);
    cudaGetSymbolAddress((void**)&p_xl2, d_xl2);
    cudaGetSymbolAddress((void**)&p_xr2, d_xr2);

    // ---- CSR build + weight split ----
    zero_kernel<<<(NN * 4 + 255) / 256, 256>>>();
    hist_kernel<<<(NE + 255) / 256, 256>>>(ei, eattr);
    scan_part_kernel<<<NSCAN, 256>>>();
    scan_top_kernel<<<1, 64>>>();
    scatter_kernel<<<(NE + 255) / 256, 256>>>(ei, eattr);
    split_w_kernel<<<(WTOT + 255) / 256, 256>>>(Wl1, Wr1, Wl2, Wr2);

    // ---- layer 1 ----
    split_x_kernel<<<(NN * 128 + 255) / 256, 256>>>(x, NN * 128);
    gemm_tf32_dual_kernel<128><<<(NN + 127) / 128, 256>>>(bl1, br1, WOFF_L1, WOFF_R1, p_xl1, p_xr1);
    gather1_kernel<<<(NN * 32 + 255) / 256, 256>>>(We1, att1, b1);

    // ---- layer 2 ----
    split_x_kernel<<<(NN * 128 + 255) / 256, 256>>>(p_h1, NN * 128);
    gemm_tf32_dual_kernel<64><<<(NN + 127) / 128, 256>>>(bl2, br2, WOFF_L2, WOFF_R2, p_xl2, p_xr2);
    gather2_kernel<<<(NN * 32 + 255) / 256, 256>>>(We2, att2, b2, batch);

    // ---- head ----
    head_kernel<<<NG, 32>>>(u, Wlin, blin, Wh, bh, out);
}

// round 11
// speedup vs baseline: 2.4503x; 1.1337x over previous
#include <cuda_runtime.h>

#define NN 50000
#define NE 800000
#define NT 850000
#define NG 512
#define SCAN_BLK 1024
#define NSCAN ((NN + SCAN_BLK - 1) / SCAN_BLK)   // 49

// W pack offsets (elements) in d_whi/d_wlo
#define WOFF_L1 0
#define WOFF_R1 16384
#define WOFF_L2 32768
#define WOFF_R2 40960
#define WTOT    49152

// ---------------- scratch (device globals; no allocation allowed) ----------------
__device__ __align__(16) float d_xl1[NN * 128];
__device__ __align__(16) float d_xr1[NN * 128];
__device__ __align__(16) float d_h1[NN * 128];
__device__ __align__(16) float d_xl2[NN * 64];
__device__ __align__(16) float d_xr2[NN * 64];
__device__ __align__(16) float d_whi[WTOT];
__device__ __align__(16) float d_wlo[WTOT];
__device__ __align__(16) float4 d_rec[NT];      // CSR records: {src_as_float, a0, a1, a2}
__device__ __align__(16) float4 d_degattr[NN];  // {cnt_as_float, sum_a0, sum_a1, sum_a2}
__device__ int   d_off[NN];                     // CSR start offset (block-local before boff add)
__device__ int   d_fill[NN];
__device__ int   d_bsum[NSCAN];
__device__ int   d_boff[NSCAN];
__device__ float d_pool[NG * 64];
__device__ float d_gcnt[NG];

__device__ __forceinline__ float lrelu(float m) { return (m > 0.f) ? m : 0.2f * m; }

__device__ __forceinline__ void tf32split(float v, float& hi, float& lo) {
    unsigned hb; asm("cvt.rna.tf32.f32 %0, %1;" : "=r"(hb) : "f"(v));
    hi = __uint_as_float(hb);
    float l = v - hi;
    unsigned lb; asm("cvt.rna.tf32.f32 %0, %1;" : "=r"(lb) : "f"(l));
    lo = __uint_as_float(lb);
}

__device__ __forceinline__ void mma_tf32(float* c,
                                         unsigned a0, unsigned a1, unsigned a2, unsigned a3,
                                         unsigned b0, unsigned b1) {
    asm volatile("mma.sync.aligned.m16n8k8.row.col.f32.tf32.tf32.f32 "
                 "{%0,%1,%2,%3}, {%4,%5,%6,%7}, {%8,%9}, {%0,%1,%2,%3};"
                 : "+f"(c[0]), "+f"(c[1]), "+f"(c[2]), "+f"(c[3])
                 : "r"(a0), "r"(a1), "r"(a2), "r"(a3), "r"(b0), "r"(b1));
}

// ---------------- streams/events for captured fork-join (created once at load) ----------------
static cudaStream_t g_s1;
static cudaEvent_t  g_evFork, g_evJoin;
namespace {
struct _StreamInit {
    _StreamInit() {
        cudaStreamCreateWithFlags(&g_s1, cudaStreamNonBlocking);
        cudaEventCreateWithFlags(&g_evFork, cudaEventDisableTiming);
        cudaEventCreateWithFlags(&g_evJoin, cudaEventDisableTiming);
    }
};
static _StreamInit g_streamInit;
}

// ---------------- zero init ----------------
__global__ void zero_kernel() {
    int i = blockIdx.x * 256 + threadIdx.x;
    if (i < NN * 4) reinterpret_cast<float*>(d_degattr)[i] = 0.f;
    if (i < NN)     d_fill[i] = 0;
    if (i < NG * 64) d_pool[i] = 0.f;
    if (i < NG)      d_gcnt[i] = 0.f;
}

// ---------------- histogram + self-loop attr sums: one vector RED per edge ----------------
__global__ void hist_kernel(const int* __restrict__ ei, const float* __restrict__ ea) {
    int e = blockIdx.x * 256 + threadIdx.x;
    if (e >= NE) return;
    int d = ei[NE + e];
    float a0 = ea[e * 3 + 0], a1 = ea[e * 3 + 1], a2 = ea[e * 3 + 2];
    asm volatile("red.global.add.v4.f32 [%0], {%1, %2, %3, %4};"
                 :: "l"(&d_degattr[d]), "f"(1.0f), "f"(a0), "f"(a1), "f"(a2)
                 : "memory");
}

// ---------------- 2-level exclusive scan of cnt[v] ----------------
__global__ void scan_part_kernel() {
    __shared__ int wsum[8];
    __shared__ int woff[8];
    int b = blockIdx.x, t = threadIdx.x;
    int lane = t & 31, wid = t >> 5;
    int base = b * SCAN_BLK + t * 4;
    int v0 = (base + 0 < NN) ? (int)d_degattr[base + 0].x : 0;
    int v1 = (base + 1 < NN) ? (int)d_degattr[base + 1].x : 0;
    int v2 = (base + 2 < NN) ? (int)d_degattr[base + 2].x : 0;
    int v3 = (base + 3 < NN) ? (int)d_degattr[base + 3].x : 0;
    int tsum = v0 + v1 + v2 + v3;
    int x = tsum;
#pragma unroll
    for (int o = 1; o < 32; o <<= 1) {
        int y = __shfl_up_sync(0xffffffffu, x, o);
        if (lane >= o) x += y;
    }
    if (lane == 31) wsum[wid] = x;
    __syncthreads();
    if (t == 0) {
        int r = 0;
#pragma unroll
        for (int i = 0; i < 8; i++) { woff[i] = r; r += wsum[i]; }
        d_bsum[b] = r;
    }
    __syncthreads();
    int excl = x - tsum + woff[wid];
    if (base + 0 < NN) d_off[base + 0] = excl;
    if (base + 1 < NN) d_off[base + 1] = excl + v0;
    if (base + 2 < NN) d_off[base + 2] = excl + v0 + v1;
    if (base + 3 < NN) d_off[base + 3] = excl + v0 + v1 + v2;
}

__global__ void scan_top_kernel() {
    __shared__ int s[NSCAN];
    int t = threadIdx.x;
    if (t < NSCAN) s[t] = d_bsum[t];
    __syncthreads();
    if (t == 0) {
        int r = 0;
        for (int i = 0; i < NSCAN; i++) { int v = s[i]; s[i] = r; r += v; }
    }
    __syncthreads();
    if (t < NSCAN) d_boff[t] = s[t];
}

// scatter real edges into CSR (final offset computed inline)
__global__ void scatter_kernel(const int* __restrict__ ei, const float* __restrict__ ea) {
    int e = blockIdx.x * 256 + threadIdx.x;
    if (e >= NE) return;
    int s = ei[e], d = ei[NE + e];
    int slot = d_off[d] + d_boff[d >> 10] + atomicAdd(&d_fill[d], 1);
    float4 r;
    r.x = __int_as_float(s);
    r.y = ea[e * 3 + 0];
    r.z = ea[e * 3 + 1];
    r.w = ea[e * 3 + 2];
    d_rec[slot] = r;
}

// ---------------- tf32 hi/lo split for the (small) weight matrices ----------------
__global__ void split_w_kernel(const float* __restrict__ Wl1, const float* __restrict__ Wr1,
                               const float* __restrict__ Wl2, const float* __restrict__ Wr2) {
    int i = blockIdx.x * 256 + threadIdx.x;
    if (i >= WTOT) return;
    float v;
    if (i < WOFF_R1)      v = Wl1[i];
    else if (i < WOFF_L2) v = Wr1[i - WOFF_R1];
    else if (i < WOFF_R2) v = Wl2[i - WOFF_L2];
    else                  v = Wr2[i - WOFF_R2];
    float hi, lo; tf32split(v, hi, lo);
    d_whi[i] = hi; d_wlo[i] = lo;
}

// ---------------- tf32 tensor-core dual GEMM with in-register X split ----------------
// K = 128. Block 256 thr (8 warps); block tile 128 nodes x M. Warp tile 16 nodes x M.
// 3xTF32: acc += Al*Bh + Ah*Bl + Ah*Bh. X loaded as fp32 and split while staging smem.
template<int M>
__global__ __launch_bounds__(256, 2)
void gemm_tf32_dual_kernel(const float* __restrict__ X,
                           const float* __restrict__ ba, const float* __restrict__ bb,
                           int wOffA, int wOffB,
                           float* __restrict__ Ya, float* __restrict__ Yb) {
    const int KP = 20;                         // padded k-stride (conflict-free)
    __shared__ float sXh[128 * KP], sXl[128 * KP];
    __shared__ float sWh[M * KP],   sWl[M * KP];
    const int tid = threadIdx.x;
    const int warp = tid >> 5, lane = tid & 31;
    const int g = lane >> 2, tig = lane & 3;
    const int base = blockIdx.x * 128;
    const int NTILE = M / 8;

#pragma unroll
    for (int phase = 0; phase < 2; phase++) {
        const float* Wh_ = d_whi + (phase ? wOffB : wOffA);
        const float* Wl_ = d_wlo + (phase ? wOffB : wOffA);
        const float* bp  = phase ? bb : ba;
        float* Yp        = phase ? Yb : Ya;

        float acc[NTILE][4];
#pragma unroll
        for (int nt = 0; nt < NTILE; nt++)
#pragma unroll
            for (int q = 0; q < 4; q++) acc[nt][q] = 0.f;

        for (int kc = 0; kc < 8; kc++) {
            __syncthreads();
            // stage X chunk [128 nodes x 16 k]: load fp32, split hi/lo in-register
            for (int i = tid; i < 512; i += 256) {
                int row = i >> 2, c4 = (i & 3) * 4;
                int node = base + row;
                float4 v = make_float4(0.f, 0.f, 0.f, 0.f);
                if (node < NN)
                    v = *reinterpret_cast<const float4*>(&X[node * 128 + kc * 16 + c4]);
                float4 vh, vl;
                tf32split(v.x, vh.x, vl.x);
                tf32split(v.y, vh.y, vl.y);
                tf32split(v.z, vh.z, vl.z);
                tf32split(v.w, vh.w, vl.w);
                *reinterpret_cast<float4*>(&sXh[row * KP + c4]) = vh;
                *reinterpret_cast<float4*>(&sXl[row * KP + c4]) = vl;
            }
            // stage W chunk [M x 16 k], pre-split hi+lo
            for (int i = tid; i < M * 4; i += 256) {
                int row = i >> 2, c4 = (i & 3) * 4;
                *reinterpret_cast<float4*>(&sWh[row * KP + c4]) =
                    *reinterpret_cast<const float4*>(&Wh_[row * 128 + kc * 16 + c4]);
                *reinterpret_cast<float4*>(&sWl[row * KP + c4]) =
                    *reinterpret_cast<const float4*>(&Wl_[row * 128 + kc * 16 + c4]);
            }
            __syncthreads();

#pragma unroll
            for (int ks = 0; ks < 2; ks++) {
                int k0 = ks * 8;
                int ar = warp * 16 + g;
                unsigned ah0 = __float_as_uint(sXh[ar * KP + k0 + tig]);
                unsigned ah1 = __float_as_uint(sXh[(ar + 8) * KP + k0 + tig]);
                unsigned ah2 = __float_as_uint(sXh[ar * KP + k0 + tig + 4]);
                unsigned ah3 = __float_as_uint(sXh[(ar + 8) * KP + k0 + tig + 4]);
                unsigned al0 = __float_as_uint(sXl[ar * KP + k0 + tig]);
                unsigned al1 = __float_as_uint(sXl[(ar + 8) * KP + k0 + tig]);
                unsigned al2 = __float_as_uint(sXl[ar * KP + k0 + tig + 4]);
                unsigned al3 = __float_as_uint(sXl[(ar + 8) * KP + k0 + tig + 4]);
#pragma unroll
                for (int nt = 0; nt < NTILE; nt++) {
                    int bn = nt * 8 + g;
                    unsigned bh0 = __float_as_uint(sWh[bn * KP + k0 + tig]);
                    unsigned bh1 = __float_as_uint(sWh[bn * KP + k0 + tig + 4]);
                    unsigned bl0 = __float_as_uint(sWl[bn * KP + k0 + tig]);
                    unsigned bl1 = __float_as_uint(sWl[bn * KP + k0 + tig + 4]);
                    mma_tf32(acc[nt], al0, al1, al2, al3, bh0, bh1);  // Al*Bh
                    mma_tf32(acc[nt], ah0, ah1, ah2, ah3, bl0, bl1);  // Ah*Bl
                    mma_tf32(acc[nt], ah0, ah1, ah2, ah3, bh0, bh1);  // Ah*Bh
                }
            }
        }

        // store with bias
        int r0 = base + warp * 16 + g;
#pragma unroll
        for (int nt = 0; nt < NTILE; nt++) {
            int col = nt * 8 + tig * 2;
            float bx = __ldg(&bp[col]), by = __ldg(&bp[col + 1]);
            if (r0 < NN) {
                float2 o; o.x = acc[nt][0] + bx; o.y = acc[nt][1] + by;
                *reinterpret_cast<float2*>(&Yp[r0 * M + col]) = o;
            }
            if (r0 + 8 < NN) {
                float2 o; o.x = acc[nt][2] + bx; o.y = acc[nt][3] + by;
                *reinterpret_cast<float2*>(&Yp[(r0 + 8) * M + col]) = o;
            }
        }
        __syncthreads();   // protect smem before next phase restage
    }
}

// ---------------- layer 1 gather: warp per dst node, fully fused, self-loop inline ----------------
__global__ void gather1_kernel(const float* __restrict__ We, const float* __restrict__ att,
                               const float* __restrict__ b1) {
    __shared__ float sWe[128 * 3];
    __shared__ __align__(16) float sAtt[128];
    __shared__ __align__(16) float sB[128];
    int tid = threadIdx.x;
    for (int i = tid; i < 384; i += 256) sWe[i] = We[i];
    for (int i = tid; i < 128; i += 256) { sAtt[i] = att[i]; sB[i] = b1[i]; }
    __syncthreads();

    int v = (blockIdx.x * 256 + tid) >> 5;
    if (v >= NN) return;
    int lane = tid & 31;
    int j0 = lane * 4;

    float4 xr = *reinterpret_cast<const float4*>(&d_xr1[v * 128 + j0]);
    float4 at = *reinterpret_cast<const float4*>(&sAtt[j0]);
    float w0 = sWe[j0*3+0], w1 = sWe[j0*3+1], w2 = sWe[j0*3+2];
    float w3 = sWe[j0*3+3], w4 = sWe[j0*3+4], w5 = sWe[j0*3+5];
    float w6 = sWe[j0*3+6], w7 = sWe[j0*3+7], w8 = sWe[j0*3+8];
    float w9 = sWe[j0*3+9], wa = sWe[j0*3+10], wb = sWe[j0*3+11];

    int off = d_off[v] + d_boff[v >> 10];
    float4 da = d_degattr[v];
    int deg = (int)da.x;

    float a0 = 0.f, a1 = 0.f, a2 = 0.f, a3 = 0.f, den = 0.f;
    float4 rec = __ldg(&d_rec[off]);
    for (int i = 0; i < deg; i++) {
        int s = __float_as_int(rec.x);
        float ea0 = rec.y, ea1 = rec.z, ea2 = rec.w;
        if (i + 1 < deg) rec = __ldg(&d_rec[off + i + 1]);
        float4 xl = *reinterpret_cast<const float4*>(&d_xl1[s * 128 + j0]);
        float m0 = lrelu(xl.x + xr.x + w0 * ea0 + w1 * ea1 + w2 * ea2);
        float m1 = lrelu(xl.y + xr.y + w3 * ea0 + w4 * ea1 + w5 * ea2);
        float m2 = lrelu(xl.z + xr.z + w6 * ea0 + w7 * ea1 + w8 * ea2);
        float m3 = lrelu(xl.w + xr.w + w9 * ea0 + wa * ea1 + wb * ea2);
        float p = m0 * at.x + m1 * at.y + m2 * at.z + m3 * at.w;
        p += __shfl_xor_sync(0xffffffffu, p, 1);
        p += __shfl_xor_sync(0xffffffffu, p, 2);
        p += __shfl_xor_sync(0xffffffffu, p, 4);
        float w = __expf(p);
        den += w;
        a0 += w * xl.x; a1 += w * xl.y; a2 += w * xl.z; a3 += w * xl.w;
    }
    {   // self loop: src = v, attrs = mean of incoming
        float cf = fmaxf(da.x, 1.f);
        float ea0 = da.y / cf, ea1 = da.z / cf, ea2 = da.w / cf;
        float4 xl = *reinterpret_cast<const float4*>(&d_xl1[v * 128 + j0]);
        float m0 = lrelu(xl.x + xr.x + w0 * ea0 + w1 * ea1 + w2 * ea2);
        float m1 = lrelu(xl.y + xr.y + w3 * ea0 + w4 * ea1 + w5 * ea2);
        float m2 = lrelu(xl.z + xr.z + w6 * ea0 + w7 * ea1 + w8 * ea2);
        float m3 = lrelu(xl.w + xr.w + w9 * ea0 + wa * ea1 + wb * ea2);
        float p = m0 * at.x + m1 * at.y + m2 * at.z + m3 * at.w;
        p += __shfl_xor_sync(0xffffffffu, p, 1);
        p += __shfl_xor_sync(0xffffffffu, p, 2);
        p += __shfl_xor_sync(0xffffffffu, p, 4);
        float w = __expf(p);
        den += w;
        a0 += w * xl.x; a1 += w * xl.y; a2 += w * xl.z; a3 += w * xl.w;
    }
    float inv = 1.f / den;
    float4 bv = *reinterpret_cast<const float4*>(&sB[j0]);
    float o0 = a0 * inv + bv.x, o1 = a1 * inv + bv.y;
    float o2 = a2 * inv + bv.z, o3 = a3 * inv + bv.w;
    float4 o;
    o.x = (o0 > 0.f) ? o0 : (__expf(o0) - 1.f);
    o.y = (o1 > 0.f) ? o1 : (__expf(o1) - 1.f);
    o.z = (o2 > 0.f) ? o2 : (__expf(o2) - 1.f);
    o.w = (o3 > 0.f) ? o3 : (__expf(o3) - 1.f);
    *reinterpret_cast<float4*>(&d_h1[v * 128 + j0]) = o;
}

// ---------------- layer 2 gather + pooled accumulation ----------------
__global__ void gather2_kernel(const float* __restrict__ We, const float* __restrict__ att,
                               const float* __restrict__ b2, const int* __restrict__ batch) {
    __shared__ float sWe[64 * 3];
    __shared__ __align__(8) float sAtt[64];
    __shared__ __align__(8) float sB[64];
    int tid = threadIdx.x;
    for (int i = tid; i < 192; i += 256) sWe[i] = We[i];
    for (int i = tid; i < 64; i += 256) { sAtt[i] = att[i]; sB[i] = b2[i]; }
    __syncthreads();

    int v = (blockIdx.x * 256 + tid) >> 5;
    if (v >= NN) return;
    int lane = tid & 31;
    int j0 = lane * 2;

    float2 xr = *reinterpret_cast<const float2*>(&d_xr2[v * 64 + j0]);
    float2 at = *reinterpret_cast<const float2*>(&sAtt[j0]);
    float w0 = sWe[j0*3+0], w1 = sWe[j0*3+1], w2 = sWe[j0*3+2];
    float w3 = sWe[j0*3+3], w4 = sWe[j0*3+4], w5 = sWe[j0*3+5];

    int off = d_off[v] + d_boff[v >> 10];
    float4 da = d_degattr[v];
    int deg = (int)da.x;

    float a0 = 0.f, a1 = 0.f, den = 0.f;
    float4 rec = __ldg(&d_rec[off]);
    for (int i = 0; i < deg; i++) {
        int s = __float_as_int(rec.x);
        float ea0 = rec.y, ea1 = rec.z, ea2 = rec.w;
        if (i + 1 < deg) rec = __ldg(&d_rec[off + i + 1]);
        float2 xl = *reinterpret_cast<const float2*>(&d_xl2[s * 64 + j0]);
        float m0 = lrelu(xl.x + xr.x + w0 * ea0 + w1 * ea1 + w2 * ea2);
        float m1 = lrelu(xl.y + xr.y + w3 * ea0 + w4 * ea1 + w5 * ea2);
        float p = m0 * at.x + m1 * at.y;
#pragma unroll
        for (int o = 16; o > 0; o >>= 1) p += __shfl_xor_sync(0xffffffffu, p, o);
        float w = __expf(p);
        den += w;
        a0 += w * xl.x; a1 += w * xl.y;
    }
    {   // self loop
        float cf = fmaxf(da.x, 1.f);
        float ea0 = da.y / cf, ea1 = da.z / cf, ea2 = da.w / cf;
        float2 xl = *reinterpret_cast<const float2*>(&d_xl2[v * 64 + j0]);
        float m0 = lrelu(xl.x + xr.x + w0 * ea0 + w1 * ea1 + w2 * ea2);
        float m1 = lrelu(xl.y + xr.y + w3 * ea0 + w4 * ea1 + w5 * ea2);
        float p = m0 * at.x + m1 * at.y;
#pragma unroll
        for (int o = 16; o > 0; o >>= 1) p += __shfl_xor_sync(0xffffffffu, p, o);
        float w = __expf(p);
        den += w;
        a0 += w * xl.x; a1 += w * xl.y;
    }
    float inv = 1.f / den;
    float o0 = a0 * inv + sB[j0], o1 = a1 * inv + sB[j0 + 1];
    o0 = (o0 > 0.f) ? o0 : (__expf(o0) - 1.f);
    o1 = (o1 > 0.f) ? o1 : (__expf(o1) - 1.f);
    int g = __ldg(&batch[v]);
    asm volatile("red.global.add.v2.f32 [%0], {%1, %2};"
                 :: "l"(&d_pool[g * 64 + j0]), "f"(o0), "f"(o1) : "memory");
    if (lane == 0) atomicAdd(&d_gcnt[g], 1.f);
}

// ---------------- head MLP ----------------
__global__ void head_kernel(const float* __restrict__ u,
                            const float* __restrict__ Wl, const float* __restrict__ bl,
                            const float* __restrict__ Wh, const float* __restrict__ bh,
                            float* __restrict__ out) {
    int g = blockIdx.x;
    int j = threadIdx.x;  // 32 threads
    __shared__ float pin[64];
    __shared__ float z[32];
    float cnt = fmaxf(d_gcnt[g], 1.f);
    for (int k = j; k < 64; k += 32) pin[k] = d_pool[g * 64 + k] / cnt;
    __syncthreads();
    float a = __ldg(&bl[j]);
#pragma unroll 8
    for (int k = 0; k < 64; k++) a += pin[k] * __ldg(&Wl[j * 65 + k]);
    a += __ldg(&u[g]) * __ldg(&Wl[j * 65 + 64]);
    z[j] = fmaxf(a, 0.f);
    __syncthreads();
    if (j < 10) {
        float o = __ldg(&bh[j]);
#pragma unroll
        for (int k = 0; k < 32; k++) o += z[k] * __ldg(&Wh[j * 32 + k]);
        out[g * 10 + j] = o;
    }
}

// ---------------- launch ----------------
extern "C" void kernel_launch(void* const* d_in, const int* in_sizes, int n_in,
                              void* d_out, int out_size) {
    const float* x     = (const float*)d_in[0];
    const int*   ei    = (const int*)d_in[1];
    const float* eattr = (const float*)d_in[2];
    const int*   batch = (const int*)d_in[3];
    const float* u     = (const float*)d_in[4];
    const float* Wl1   = (const float*)d_in[5];
    const float* bl1   = (const float*)d_in[6];
    const float* Wr1   = (const float*)d_in[7];
    const float* br1   = (const float*)d_in[8];
    const float* We1   = (const float*)d_in[9];
    const float* att1  = (const float*)d_in[10];
    const float* b1    = (const float*)d_in[11];
    const float* Wl2   = (const float*)d_in[12];
    const float* bl2   = (const float*)d_in[13];
    const float* Wr2   = (const float*)d_in[14];
    const float* br2   = (const float*)d_in[15];
    const float* We2   = (const float*)d_in[16];
    const float* att2  = (const float*)d_in[17];
    const float* b2    = (const float*)d_in[18];
    const float* Wlin  = (const float*)d_in[19];
    const float* blin  = (const float*)d_in[20];
    const float* Wh    = (const float*)d_in[21];
    const float* bh    = (const float*)d_in[22];
    float* out = (float*)d_out;

    float *p_xl1, *p_xr1, *p_h1, *p_xl2, *p_xr2;
    cudaGetSymbolAddress((void**)&p_xl1, d_xl1);
    cudaGetSymbolAddress((void**)&p_xr1, d_xr1);
    cudaGetSymbolAddress((void**)&p_h1,  d_h1);
    cudaGetSymbolAddress((void**)&p_xl2, d_xl2);
    cudaGetSymbolAddress((void**)&p_xr2, d_xr2);

    // ---- fork: CSR build on g_s1, GEMM path on default stream ----
    cudaEventRecord(g_evFork, 0);
    cudaStreamWaitEvent(g_s1, g_evFork, 0);

    // side stream: CSR build chain
    zero_kernel<<<(NN * 4 + 255) / 256, 256, 0, g_s1>>>();
    hist_kernel<<<(NE + 255) / 256, 256, 0, g_s1>>>(ei, eattr);
    scan_part_kernel<<<NSCAN, 256, 0, g_s1>>>();
    scan_top_kernel<<<1, 64, 0, g_s1>>>();
    scatter_kernel<<<(NE + 255) / 256, 256, 0, g_s1>>>(ei, eattr);
    cudaEventRecord(g_evJoin, g_s1);

    // default stream: weight split + layer-1 dual GEMM (independent of CSR)
    split_w_kernel<<<(WTOT + 255) / 256, 256>>>(Wl1, Wr1, Wl2, Wr2);
    gemm_tf32_dual_kernel<128><<<(NN + 127) / 128, 256>>>(x, bl1, br1, WOFF_L1, WOFF_R1, p_xl1, p_xr1);

    // join: gather1 needs CSR + GEMM outputs
    cudaStreamWaitEvent(0, g_evJoin, 0);
    gather1_kernel<<<(NN * 32 + 255) / 256, 256>>>(We1, att1, b1);

    // ---- layer 2 ----
    gemm_tf32_dual_kernel<64><<<(NN + 127) / 128, 256>>>(p_h1, bl2, br2, WOFF_L2, WOFF_R2, p_xl2, p_xr2);
    gather2_kernel<<<(NN * 32 + 255) / 256, 256>>>(We2, att2, b2, batch);

    // ---- head ----
    head_kernel<<<NG, 32>>>(u, Wlin, blin, Wh, bh, out);
}